// round 10
// baseline (speedup 1.0000x reference)
#include <cuda_runtime.h>
#include <cuda_bf16.h>
#include <cstdint>

#define N_NODES 50000
#define N_EDGES 800000
#define DIM     128
#define N_GRAPHS 64
#define N_CLASS  10
#define HID      64
#define SCAN_BLOCKS 196   // ceil(50000/256)
#define N_TILES 391       // ceil(50000/128)
#define N_PAD   (N_TILES * 128)
#define SA      136       // padded K-stride in smem (bank-conflict-free fragments)

// ---------------- device scratch ----------------
__device__ float g_h[2][N_NODES * DIM];
__device__ unsigned short g_Ahi[N_PAD * DIM];   // row-major bf16 hi of aggregated feats
__device__ unsigned short g_Alo[N_PAD * DIM];   // row-major bf16 lo
__device__ unsigned short g_Whi[6 * DIM * DIM]; // row-major W^T [N][K] bf16 hi
__device__ unsigned short g_Wlo[6 * DIM * DIM];
__device__ float g_ns[N_NODES];
__device__ float g_nd[N_NODES];
__device__ int   g_indeg[N_NODES];
__device__ int   g_outdeg[N_NODES];
__device__ int   g_rowptr[N_NODES + 1];
__device__ int   g_cursor[N_NODES];
__device__ int   g_csrsrc[N_EDGES];
__device__ float g_pooled[N_GRAPHS * DIM];
__device__ int   g_gcount[N_GRAPHS];

__device__ __forceinline__ void split_bf(float x, unsigned short& hi, unsigned short& lo) {
    __nv_bfloat16 h = __float2bfloat16_rn(x);
    hi = __bfloat16_as_ushort(h);
    lo = __bfloat16_as_ushort(__float2bfloat16_rn(x - __bfloat162float(h)));
}

__device__ __forceinline__ void mma16816(float* c, const uint32_t* a, const uint32_t* b) {
    asm volatile(
        "mma.sync.aligned.m16n8k16.row.col.f32.bf16.bf16.f32 "
        "{%0,%1,%2,%3}, {%4,%5,%6,%7}, {%8,%9}, {%0,%1,%2,%3};"
        : "+f"(c[0]), "+f"(c[1]), "+f"(c[2]), "+f"(c[3])
        : "r"(a[0]), "r"(a[1]), "r"(a[2]), "r"(a[3]), "r"(b[0]), "r"(b[1]));
}

__device__ __forceinline__ void cp16(void* dst, const void* src) {
    uint32_t d = (uint32_t)__cvta_generic_to_shared(dst);
    asm volatile("cp.async.cg.shared.global [%0], [%1], 16;" :: "r"(d), "l"(src));
}

// ---------------- setup: zero counters + tail tiles + weight conversion (one launch) ----------------
__global__ void setup_kernel(const float* W0, const float* W1, const float* W2,
                             const float* W3, const float* W4, const float* W5) {
    int idx = blockIdx.x * 256 + threadIdx.x;
    if (idx < N_NODES) { g_indeg[idx] = 0; g_outdeg[idx] = 0; g_cursor[idx] = 0; }
    if (idx < N_GRAPHS * DIM) g_pooled[idx] = 0.0f;
    if (idx < N_GRAPHS) g_gcount[idx] = 0;
    if (idx < 768) ((uint4*)(g_Ahi + N_NODES * DIM))[idx] = make_uint4(0, 0, 0, 0);
    else if (idx < 1536) ((uint4*)(g_Alo + N_NODES * DIM))[idx - 768] = make_uint4(0, 0, 0, 0);

    int layer = idx >> 14;
    int r = idx & 16383;
    int n = r >> 7, k = r & 127;
    const float* Ws[6] = {W0, W1, W2, W3, W4, W5};
    float val = Ws[layer][k * DIM + n];
    unsigned short hi, lo;
    split_bf(val, hi, lo);
    g_Whi[idx] = hi;
    g_Wlo[idx] = lo;
}

// ---------------- degrees: 4 edges/thread via int4 loads ----------------
__global__ void degree_kernel(const int* __restrict__ src, const int* __restrict__ dst) {
    int t = blockIdx.x * blockDim.x + threadIdx.x;
    if (t >= N_EDGES / 4) return;
    int4 s4 = ((const int4*)src)[t];
    int4 d4 = ((const int4*)dst)[t];
    atomicAdd(&g_outdeg[s4.x], 1);
    atomicAdd(&g_outdeg[s4.y], 1);
    atomicAdd(&g_outdeg[s4.z], 1);
    atomicAdd(&g_outdeg[s4.w], 1);
    atomicAdd(&g_indeg[d4.x], 1);
    atomicAdd(&g_indeg[d4.y], 1);
    atomicAdd(&g_indeg[d4.z], 1);
    atomicAdd(&g_indeg[d4.w], 1);
}

// ---------------- norm + full exclusive scan of indeg -> rowptr, ONE launch ----------------
__global__ void scanfull_kernel() {
    __shared__ int ws[8];
    __shared__ int s[256];
    __shared__ int boff_sh;
    int t = threadIdx.x;
    int base = blockIdx.x * 256;
    int i = base + t;

    if (i < N_NODES) {
        g_ns[i] = rsqrtf((float)max(g_outdeg[i], 1));
        g_nd[i] = rsqrtf((float)max(g_indeg[i], 1));
    }

    int part = 0;
    for (int j = t; j < base; j += 256) part += g_indeg[j];
#pragma unroll
    for (int o = 16; o; o >>= 1) part += __shfl_down_sync(0xffffffffu, part, o);
    if ((t & 31) == 0) ws[t >> 5] = part;

    int v = (i < N_NODES) ? g_indeg[i] : 0;
    s[t] = v;
    __syncthreads();
    if (t == 0) {
        int b = 0;
#pragma unroll
        for (int w = 0; w < 8; w++) b += ws[w];
        boff_sh = b;
    }
    __syncthreads();
    int boff = boff_sh;

    for (int o = 1; o < 256; o <<= 1) {
        int x = (t >= o) ? s[t - o] : 0;
        __syncthreads();
        s[t] += x;
        __syncthreads();
    }
    if (i < N_NODES) {
        int r = boff + s[t] - v;
        g_rowptr[i] = r;
        if (i == N_NODES - 1) g_rowptr[N_NODES] = r + v;
    }
}

// ---------------- CSR fill: 4 edges/thread, batched independent atomics ----------------
__global__ void fill_csr(const int* __restrict__ src, const int* __restrict__ dst) {
    int t = blockIdx.x * blockDim.x + threadIdx.x;
    if (t >= N_EDGES / 4) return;
    int4 s4 = ((const int4*)src)[t];
    int4 d4 = ((const int4*)dst)[t];
    int o0 = atomicAdd(&g_cursor[d4.x], 1);
    int o1 = atomicAdd(&g_cursor[d4.y], 1);
    int o2 = atomicAdd(&g_cursor[d4.z], 1);
    int o3 = atomicAdd(&g_cursor[d4.w], 1);
    int r0 = g_rowptr[d4.x];
    int r1 = g_rowptr[d4.y];
    int r2 = g_rowptr[d4.z];
    int r3 = g_rowptr[d4.w];
    g_csrsrc[r0 + o0] = s4.x;
    g_csrsrc[r1 + o1] = s4.y;
    g_csrsrc[r2 + o2] = s4.z;
    g_csrsrc[r3 + o3] = s4.w;
}

// ---------------- aggregation: one warp per destination node, 4x unrolled ----------------
template <int SRC_NORM, int DST_NORM, int OUT_BF16>
__global__ void aggregate_kernel(const float* __restrict__ ext_in, int in_sel,
                                 float* __restrict__ ext_out) {
    const float* hin = (in_sel == 0) ? g_h[0] : (in_sel == 1) ? g_h[1] : ext_in;

    int v = (blockIdx.x * blockDim.x + threadIdx.x) >> 5;
    if (v >= N_NODES) return;
    int lane = threadIdx.x & 31;

    int beg = g_rowptr[v];
    int end = g_rowptr[v + 1];

    const float4* h4 = (const float4*)hin;
    float4 acc = make_float4(0.f, 0.f, 0.f, 0.f);

    int i = beg;
    for (; i + 4 <= end; i += 4) {
        int s0 = g_csrsrc[i + 0];
        int s1 = g_csrsrc[i + 1];
        int s2 = g_csrsrc[i + 2];
        int s3 = g_csrsrc[i + 3];
        float w0 = SRC_NORM ? g_ns[s0] : 1.0f;
        float w1 = SRC_NORM ? g_ns[s1] : 1.0f;
        float w2 = SRC_NORM ? g_ns[s2] : 1.0f;
        float w3 = SRC_NORM ? g_ns[s3] : 1.0f;
        float4 v0 = h4[s0 * 32 + lane];
        float4 v1 = h4[s1 * 32 + lane];
        float4 v2 = h4[s2 * 32 + lane];
        float4 v3 = h4[s3 * 32 + lane];
        acc.x += w0 * v0.x; acc.y += w0 * v0.y; acc.z += w0 * v0.z; acc.w += w0 * v0.w;
        acc.x += w1 * v1.x; acc.y += w1 * v1.y; acc.z += w1 * v1.z; acc.w += w1 * v1.w;
        acc.x += w2 * v2.x; acc.y += w2 * v2.y; acc.z += w2 * v2.z; acc.w += w2 * v2.w;
        acc.x += w3 * v3.x; acc.y += w3 * v3.y; acc.z += w3 * v3.z; acc.w += w3 * v3.w;
    }
    for (; i < end; i++) {
        int s = g_csrsrc[i];
        float w = SRC_NORM ? g_ns[s] : 1.0f;
        float4 vv = h4[s * 32 + lane];
        acc.x += w * vv.x; acc.y += w * vv.y; acc.z += w * vv.z; acc.w += w * vv.w;
    }
    if (DST_NORM) {
        float sc = g_nd[v];
        acc.x *= sc; acc.y *= sc; acc.z *= sc; acc.w *= sc;
    }

    if (OUT_BF16) {
        unsigned short h0, h1, h2, h3, l0, l1, l2, l3;
        split_bf(acc.x, h0, l0); split_bf(acc.y, h1, l1);
        split_bf(acc.z, h2, l2); split_bf(acc.w, h3, l3);
        uint2 hv = make_uint2((uint32_t)h0 | ((uint32_t)h1 << 16),
                              (uint32_t)h2 | ((uint32_t)h3 << 16));
        uint2 lv = make_uint2((uint32_t)l0 | ((uint32_t)l1 << 16),
                              (uint32_t)l2 | ((uint32_t)l3 << 16));
        *(uint2*)&g_Ahi[(size_t)v * DIM + lane * 4] = hv;
        *(uint2*)&g_Alo[(size_t)v * DIM + lane * 4] = lv;
    } else {
        ((float4*)ext_out)[v * 32 + lane] = acc;
    }
}

// ---------------- tensor-core GEMM: cp.async 2-stage k-pipelined staging ----------------
// g_h[out_buf][row] = relu(A[row] @ W + b) * (do_ps ? g_ns[row] : 1)
// CTA: 128 rows x 128 cols, 8 warps (4M x 2N), warp tile 32x64.
__global__ void __launch_bounds__(256, 1) gemm_mma(
    const float* __restrict__ b, int layer, int out_buf, int do_ps) {
    extern __shared__ __align__(16) unsigned short sm[];
    unsigned short* sAh = sm;
    unsigned short* sAl = sm + 128 * SA;
    unsigned short* sWh = sm + 2 * 128 * SA;
    unsigned short* sWl = sm + 3 * 128 * SA;

    int tid = threadIdx.x;
    const uint4* gAh = (const uint4*)(g_Ahi + (size_t)blockIdx.x * (128 * DIM));
    const uint4* gAl = (const uint4*)(g_Alo + (size_t)blockIdx.x * (128 * DIM));
    const uint4* gWh = (const uint4*)(g_Whi + (size_t)layer * (DIM * DIM));
    const uint4* gWl = (const uint4*)(g_Wlo + (size_t)layer * (DIM * DIM));

    // stage k-half h = columns [h*64, h*64+64): 1024 uint4 per buffer, 4/thread
#pragma unroll
    for (int h = 0; h < 2; h++) {
#pragma unroll
        for (int it = 0; it < 4; it++) {
            int i = tid + it * 256;         // 0..1023
            int r = i >> 3, c = i & 7;      // row, uint4-col within half
            int gi = r * 16 + h * 8 + c;    // gmem uint4 index
            int so = r * SA + h * 64 + c * 8;  // smem ushort offset
            cp16(&sAh[so], &gAh[gi]);
            cp16(&sAl[so], &gAl[gi]);
            cp16(&sWh[so], &gWh[gi]);
            cp16(&sWl[so], &gWl[gi]);
        }
        asm volatile("cp.async.commit_group;" ::: "memory");
    }

    int warp = tid >> 5, lane = tid & 31;
    int wm = warp & 3, wn = warp >> 2;           // 4 M-warps x 2 N-warps
    int bm = wm * 32, bn = wn * 64;
    int lr = lane >> 2, lc = (lane & 3) * 2;

    float acc[2][8][4];
#pragma unroll
    for (int mi = 0; mi < 2; mi++)
#pragma unroll
        for (int ni = 0; ni < 8; ni++)
#pragma unroll
            for (int q = 0; q < 4; q++) acc[mi][ni][q] = 0.f;

#pragma unroll
    for (int half = 0; half < 2; half++) {
        if (half == 0) {
            asm volatile("cp.async.wait_group 1;" ::: "memory");
        } else {
            asm volatile("cp.async.wait_group 0;" ::: "memory");
        }
        __syncthreads();

#pragma unroll
        for (int kk = 0; kk < 4; kk++) {
            int k0 = (half * 4 + kk) * 16;
            uint32_t afh[2][4], afl[2][4], bfh[8][2], bfl[8][2];
#pragma unroll
            for (int mi = 0; mi < 2; mi++) {
                int r = bm + mi * 16 + lr;
                afh[mi][0] = *(const uint32_t*)&sAh[r * SA + k0 + lc];
                afh[mi][1] = *(const uint32_t*)&sAh[(r + 8) * SA + k0 + lc];
                afh[mi][2] = *(const uint32_t*)&sAh[r * SA + k0 + 8 + lc];
                afh[mi][3] = *(const uint32_t*)&sAh[(r + 8) * SA + k0 + 8 + lc];
                afl[mi][0] = *(const uint32_t*)&sAl[r * SA + k0 + lc];
                afl[mi][1] = *(const uint32_t*)&sAl[(r + 8) * SA + k0 + lc];
                afl[mi][2] = *(const uint32_t*)&sAl[r * SA + k0 + 8 + lc];
                afl[mi][3] = *(const uint32_t*)&sAl[(r + 8) * SA + k0 + 8 + lc];
            }
#pragma unroll
            for (int ni = 0; ni < 8; ni++) {
                int cc = bn + ni * 8 + lr;
                bfh[ni][0] = *(const uint32_t*)&sWh[cc * SA + k0 + lc];
                bfh[ni][1] = *(const uint32_t*)&sWh[cc * SA + k0 + 8 + lc];
                bfl[ni][0] = *(const uint32_t*)&sWl[cc * SA + k0 + lc];
                bfl[ni][1] = *(const uint32_t*)&sWl[cc * SA + k0 + 8 + lc];
            }
#pragma unroll
            for (int mi = 0; mi < 2; mi++)
#pragma unroll
                for (int ni = 0; ni < 8; ni++) {
                    mma16816(acc[mi][ni], afh[mi], bfh[ni]);   // hi*hi
                    mma16816(acc[mi][ni], afh[mi], bfl[ni]);   // hi*lo
                    mma16816(acc[mi][ni], afl[mi], bfh[ni]);   // lo*hi
                }
        }
    }

    float* C = g_h[out_buf];
#pragma unroll
    for (int mi = 0; mi < 2; mi++) {
        int r0 = blockIdx.x * 128 + bm + mi * 16 + lr;
        int r1 = r0 + 8;
        float ps0 = 1.f, ps1 = 1.f;
        if (do_ps) {
            if (r0 < N_NODES) ps0 = g_ns[r0];
            if (r1 < N_NODES) ps1 = g_ns[r1];
        }
#pragma unroll
        for (int ni = 0; ni < 8; ni++) {
            int col = bn + ni * 8 + lc;
            float2 bv = *(const float2*)&b[col];
            if (r0 < N_NODES) {
                float2 o;
                o.x = fmaxf(acc[mi][ni][0] + bv.x, 0.f) * ps0;
                o.y = fmaxf(acc[mi][ni][1] + bv.y, 0.f) * ps0;
                *(float2*)&C[(size_t)r0 * DIM + col] = o;
            }
            if (r1 < N_NODES) {
                float2 o;
                o.x = fmaxf(acc[mi][ni][2] + bv.x, 0.f) * ps1;
                o.y = fmaxf(acc[mi][ni][3] + bv.y, 0.f) * ps1;
                *(float2*)&C[(size_t)r1 * DIM + col] = o;
            }
        }
    }
}

// ---------------- pooling: sorted graph_id -> register accumulation ----------------
__global__ void pool_kernel(int buf, const int* __restrict__ gid) {
    const float* h = g_h[buf];
    int group = blockIdx.x * 2 + (threadIdx.x >> 7);
    int d = threadIdx.x & 127;
    int start = group * 128;
    if (start >= N_NODES) return;
    int end = min(start + 128, N_NODES);

    int cur = gid[start];
    float acc = 0.f;
    int cnt = 0;
    for (int n = start; n < end; n++) {
        int g = gid[n];
        if (g != cur) {
            atomicAdd(&g_pooled[cur * DIM + d], acc);
            if (d == 0) atomicAdd(&g_gcount[cur], cnt);
            acc = 0.f; cnt = 0; cur = g;
        }
        acc += h[n * DIM + d];
        cnt++;
    }
    atomicAdd(&g_pooled[cur * DIM + d], acc);
    if (d == 0) atomicAdd(&g_gcount[cur], cnt);
}

// ---------------- head MLP ----------------
__global__ void mlp_kernel(const float* __restrict__ Wa, const float* __restrict__ ba,
                           const float* __restrict__ Wb, const float* __restrict__ bb,
                           float* __restrict__ out) {
    __shared__ float pm[N_GRAPHS * DIM];
    __shared__ float z[N_GRAPHS * HID];
    int t = threadIdx.x;

    for (int i = t; i < N_GRAPHS * DIM; i += 256) {
        int g = i / DIM;
        float cnt = fmaxf((float)g_gcount[g], 1.0f);
        pm[i] = g_pooled[i] / cnt;
    }
    __syncthreads();

    for (int i = t; i < N_GRAPHS * HID; i += 256) {
        int g = i / HID, j = i % HID;
        float s = ba[j];
        for (int d = 0; d < DIM; d++) s += pm[g * DIM + d] * Wa[d * HID + j];
        z[i] = fmaxf(s, 0.0f);
    }
    __syncthreads();

    for (int i = t; i < N_GRAPHS * N_CLASS; i += 256) {
        int g = i / N_CLASS, c = i % N_CLASS;
        float s = bb[c];
        for (int j = 0; j < HID; j++) s += z[g * HID + j] * Wb[j * N_CLASS + c];
        out[i] = s;
    }
}

// ---------------- launch ----------------
extern "C" void kernel_launch(void* const* d_in, const int* in_sizes, int n_in,
                              void* d_out, int out_size) {
    const float* feat = (const float*)d_in[0];
    const int* src = (const int*)d_in[1];
    const int* dst = (const int*)d_in[2];
    const int* gid = (const int*)d_in[3];
    const float* Ws[6] = {(const float*)d_in[4], (const float*)d_in[6], (const float*)d_in[8],
                          (const float*)d_in[10], (const float*)d_in[12], (const float*)d_in[14]};
    const float* bs[6] = {(const float*)d_in[5], (const float*)d_in[7], (const float*)d_in[9],
                          (const float*)d_in[11], (const float*)d_in[13], (const float*)d_in[15]};
    const float* Wa = (const float*)d_in[16];
    const float* ba = (const float*)d_in[17];
    const float* Wb = (const float*)d_in[18];
    const float* bb = (const float*)d_in[19];
    float* out = (float*)d_out;

    const int SMEM_DYN = 4 * 128 * SA * 2;   // 139264 B
    cudaFuncSetAttribute(gemm_mma, cudaFuncAttributeMaxDynamicSharedMemorySize, SMEM_DYN);

    // graph structure: 4 launches
    setup_kernel<<<384, 256>>>(Ws[0], Ws[1], Ws[2], Ws[3], Ws[4], Ws[5]);
    degree_kernel<<<(N_EDGES / 4 + 255) / 256, 256>>>(src, dst);
    scanfull_kernel<<<SCAN_BLOCKS, 256>>>();
    fill_csr<<<(N_EDGES / 4 + 255) / 256, 256>>>(src, dst);

    const int AGG_GRID = (N_NODES * 32 + 255) / 256;

    // Layer 0: per-edge src norm. GEMM epilogue pre-scales layers 0..4 by ns,
    // so layers 1..5 aggregate without per-edge norm loads. relu(x)*ns == relu(x*ns).
    aggregate_kernel<1, 1, 1><<<AGG_GRID, 256>>>(feat, -1, nullptr);
    gemm_mma<<<N_TILES, 256, SMEM_DYN>>>(bs[0], 0, 0, 1);

    for (int L = 1; L < 6; L++) {
        aggregate_kernel<0, 1, 1><<<AGG_GRID, 256>>>(nullptr, (L - 1) & 1, nullptr);
        gemm_mma<<<N_TILES, 256, SMEM_DYN>>>(bs[L], L, L & 1, (L < 5) ? 1 : 0);
    }
    // final features in g_h[1]

    pool_kernel<<<SCAN_BLOCKS, 256>>>(1, gid);
    mlp_kernel<<<1, 256>>>(Wa, ba, Wb, bb, out);

    // unnormalized aggregation h_agg [50000,128] (fp32 exact)
    aggregate_kernel<0, 0, 0><<<AGG_GRID, 256>>>(nullptr, 1, out + N_GRAPHS * N_CLASS);
}

// round 11
// speedup vs baseline: 1.0044x; 1.0044x over previous
#include <cuda_runtime.h>
#include <cuda_bf16.h>
#include <cstdint>

#define N_NODES 50000
#define N_EDGES 800000
#define DIM     128
#define N_GRAPHS 64
#define N_CLASS  10
#define HID      64
#define SCAN_BLOCKS 196   // ceil(50000/256)
#define N_TILES 391       // ceil(50000/128)
#define N_PAD   (N_TILES * 128)
#define SA      136       // padded K-stride in smem (bank-conflict-free fragments)

// ---------------- device scratch ----------------
__device__ float g_h[2][N_NODES * DIM];
__device__ unsigned short g_Ahi[N_PAD * DIM];   // row-major bf16 hi of aggregated feats
__device__ unsigned short g_Alo[N_PAD * DIM];   // row-major bf16 lo
__device__ unsigned short g_Whi[6 * DIM * DIM]; // row-major W^T [N][K] bf16 hi
__device__ unsigned short g_Wlo[6 * DIM * DIM];
__device__ float g_ns[N_NODES];
__device__ float g_nd[N_NODES];
__device__ int   g_indeg[N_NODES];
__device__ int   g_outdeg[N_NODES];
__device__ int   g_rowptr[N_NODES + 1];
__device__ int   g_cursor[N_NODES];   // initialized to rowptr by scanfull_kernel
__device__ int   g_csrsrc[N_EDGES];
__device__ float g_pooled[N_GRAPHS * DIM];
__device__ int   g_gcount[N_GRAPHS];

__device__ __forceinline__ void split_bf(float x, unsigned short& hi, unsigned short& lo) {
    __nv_bfloat16 h = __float2bfloat16_rn(x);
    hi = __bfloat16_as_ushort(h);
    lo = __bfloat16_as_ushort(__float2bfloat16_rn(x - __bfloat162float(h)));
}

__device__ __forceinline__ void mma16816(float* c, const uint32_t* a, const uint32_t* b) {
    asm volatile(
        "mma.sync.aligned.m16n8k16.row.col.f32.bf16.bf16.f32 "
        "{%0,%1,%2,%3}, {%4,%5,%6,%7}, {%8,%9}, {%0,%1,%2,%3};"
        : "+f"(c[0]), "+f"(c[1]), "+f"(c[2]), "+f"(c[3])
        : "r"(a[0]), "r"(a[1]), "r"(a[2]), "r"(a[3]), "r"(b[0]), "r"(b[1]));
}

// ---------------- setup: zero counters + tail tiles + weight conversion (one launch) ----------------
__global__ void setup_kernel(const float* W0, const float* W1, const float* W2,
                             const float* W3, const float* W4, const float* W5) {
    int idx = blockIdx.x * 256 + threadIdx.x;
    if (idx < N_NODES) { g_indeg[idx] = 0; g_outdeg[idx] = 0; }
    if (idx < N_GRAPHS * DIM) g_pooled[idx] = 0.0f;
    if (idx < N_GRAPHS) g_gcount[idx] = 0;
    if (idx < 768) ((uint4*)(g_Ahi + N_NODES * DIM))[idx] = make_uint4(0, 0, 0, 0);
    else if (idx < 1536) ((uint4*)(g_Alo + N_NODES * DIM))[idx - 768] = make_uint4(0, 0, 0, 0);

    int layer = idx >> 14;
    int r = idx & 16383;
    int n = r >> 7, k = r & 127;
    const float* Ws[6] = {W0, W1, W2, W3, W4, W5};
    float val = Ws[layer][k * DIM + n];
    unsigned short hi, lo;
    split_bf(val, hi, lo);
    g_Whi[idx] = hi;
    g_Wlo[idx] = lo;
}

__global__ void degree_kernel(const int* __restrict__ src, const int* __restrict__ dst) {
    int e = blockIdx.x * blockDim.x + threadIdx.x;
    if (e < N_EDGES) {
        atomicAdd(&g_outdeg[src[e]], 1);
        atomicAdd(&g_indeg[dst[e]], 1);
    }
}

// ---------------- norm + full exclusive scan of indeg -> rowptr (+cursor init), ONE launch ----------------
__global__ void scanfull_kernel() {
    __shared__ int ws[8];
    __shared__ int s[256];
    __shared__ int boff_sh;
    int t = threadIdx.x;
    int base = blockIdx.x * 256;
    int i = base + t;

    if (i < N_NODES) {
        g_ns[i] = rsqrtf((float)max(g_outdeg[i], 1));
        g_nd[i] = rsqrtf((float)max(g_indeg[i], 1));
    }

    int part = 0;
    for (int j = t; j < base; j += 256) part += g_indeg[j];
#pragma unroll
    for (int o = 16; o; o >>= 1) part += __shfl_down_sync(0xffffffffu, part, o);
    if ((t & 31) == 0) ws[t >> 5] = part;

    int v = (i < N_NODES) ? g_indeg[i] : 0;
    s[t] = v;
    __syncthreads();
    if (t == 0) {
        int b = 0;
#pragma unroll
        for (int w = 0; w < 8; w++) b += ws[w];
        boff_sh = b;
    }
    __syncthreads();
    int boff = boff_sh;

    for (int o = 1; o < 256; o <<= 1) {
        int x = (t >= o) ? s[t - o] : 0;
        __syncthreads();
        s[t] += x;
        __syncthreads();
    }
    if (i < N_NODES) {
        int r = boff + s[t] - v;
        g_rowptr[i] = r;
        g_cursor[i] = r;   // cursor starts at row offset -> fill_csr needs no rowptr load
        if (i == N_NODES - 1) g_rowptr[N_NODES] = r + v;
    }
}

// ---------------- CSR fill: cursor IS the slot (one atomic, no dependent rowptr load) ----------------
__global__ void fill_csr(const int* __restrict__ src, const int* __restrict__ dst) {
    int e = blockIdx.x * blockDim.x + threadIdx.x;
    if (e < N_EDGES) {
        int slot = atomicAdd(&g_cursor[dst[e]], 1);
        g_csrsrc[slot] = src[e];
    }
}

// ---------------- aggregation: one warp per destination node, 4x unrolled ----------------
template <int SRC_NORM, int DST_NORM, int OUT_BF16>
__global__ void aggregate_kernel(const float* __restrict__ ext_in, int in_sel,
                                 float* __restrict__ ext_out) {
    const float* hin = (in_sel == 0) ? g_h[0] : (in_sel == 1) ? g_h[1] : ext_in;

    int v = (blockIdx.x * blockDim.x + threadIdx.x) >> 5;
    if (v >= N_NODES) return;
    int lane = threadIdx.x & 31;

    int beg = g_rowptr[v];
    int end = g_rowptr[v + 1];

    const float4* h4 = (const float4*)hin;
    float4 acc = make_float4(0.f, 0.f, 0.f, 0.f);

    int i = beg;
    for (; i + 4 <= end; i += 4) {
        int s0 = g_csrsrc[i + 0];
        int s1 = g_csrsrc[i + 1];
        int s2 = g_csrsrc[i + 2];
        int s3 = g_csrsrc[i + 3];
        float w0 = SRC_NORM ? g_ns[s0] : 1.0f;
        float w1 = SRC_NORM ? g_ns[s1] : 1.0f;
        float w2 = SRC_NORM ? g_ns[s2] : 1.0f;
        float w3 = SRC_NORM ? g_ns[s3] : 1.0f;
        float4 v0 = h4[s0 * 32 + lane];
        float4 v1 = h4[s1 * 32 + lane];
        float4 v2 = h4[s2 * 32 + lane];
        float4 v3 = h4[s3 * 32 + lane];
        acc.x += w0 * v0.x; acc.y += w0 * v0.y; acc.z += w0 * v0.z; acc.w += w0 * v0.w;
        acc.x += w1 * v1.x; acc.y += w1 * v1.y; acc.z += w1 * v1.z; acc.w += w1 * v1.w;
        acc.x += w2 * v2.x; acc.y += w2 * v2.y; acc.z += w2 * v2.z; acc.w += w2 * v2.w;
        acc.x += w3 * v3.x; acc.y += w3 * v3.y; acc.z += w3 * v3.z; acc.w += w3 * v3.w;
    }
    for (; i < end; i++) {
        int s = g_csrsrc[i];
        float w = SRC_NORM ? g_ns[s] : 1.0f;
        float4 vv = h4[s * 32 + lane];
        acc.x += w * vv.x; acc.y += w * vv.y; acc.z += w * vv.z; acc.w += w * vv.w;
    }
    if (DST_NORM) {
        float sc = g_nd[v];
        acc.x *= sc; acc.y *= sc; acc.z *= sc; acc.w *= sc;
    }

    if (OUT_BF16) {
        unsigned short h0, h1, h2, h3, l0, l1, l2, l3;
        split_bf(acc.x, h0, l0); split_bf(acc.y, h1, l1);
        split_bf(acc.z, h2, l2); split_bf(acc.w, h3, l3);
        uint2 hv = make_uint2((uint32_t)h0 | ((uint32_t)h1 << 16),
                              (uint32_t)h2 | ((uint32_t)h3 << 16));
        uint2 lv = make_uint2((uint32_t)l0 | ((uint32_t)l1 << 16),
                              (uint32_t)l2 | ((uint32_t)l3 << 16));
        *(uint2*)&g_Ahi[(size_t)v * DIM + lane * 4] = hv;
        *(uint2*)&g_Alo[(size_t)v * DIM + lane * 4] = lv;
    } else {
        ((float4*)ext_out)[v * 32 + lane] = acc;
    }
}

// ---------------- tensor-core GEMM via mma.sync (bf16x2 split, fused passes) ----------------
// g_h[out_buf][row] = relu(A[row] @ W + b) * (do_ps ? g_ns[row] : 1)
// CTA: 128 rows x 128 cols, 8 warps (4M x 2N), warp tile 32x64.
__global__ void __launch_bounds__(256, 1) gemm_mma(
    const float* __restrict__ b, int layer, int out_buf, int do_ps) {
    extern __shared__ __align__(16) unsigned short sm[];
    unsigned short* sAh = sm;
    unsigned short* sAl = sm + 128 * SA;
    unsigned short* sWh = sm + 2 * 128 * SA;
    unsigned short* sWl = sm + 3 * 128 * SA;

    int tid = threadIdx.x;
    const uint4* gAh = (const uint4*)(g_Ahi + (size_t)blockIdx.x * (128 * DIM));
    const uint4* gAl = (const uint4*)(g_Alo + (size_t)blockIdx.x * (128 * DIM));
    const uint4* gWh = (const uint4*)(g_Whi + (size_t)layer * (DIM * DIM));
    const uint4* gWl = (const uint4*)(g_Wlo + (size_t)layer * (DIM * DIM));

#pragma unroll
    for (int it = 0; it < 8; it++) {
        int i = tid + it * 256;
        int r = i >> 4, c = (i & 15) << 3;
        *(uint4*)&sAh[r * SA + c] = gAh[i];
        *(uint4*)&sAl[r * SA + c] = gAl[i];
        *(uint4*)&sWh[r * SA + c] = gWh[i];
        *(uint4*)&sWl[r * SA + c] = gWl[i];
    }
    __syncthreads();

    int warp = tid >> 5, lane = tid & 31;
    int wm = warp & 3, wn = warp >> 2;           // 4 M-warps x 2 N-warps
    int bm = wm * 32, bn = wn * 64;
    int lr = lane >> 2, lc = (lane & 3) * 2;

    float acc[2][8][4];
#pragma unroll
    for (int mi = 0; mi < 2; mi++)
#pragma unroll
        for (int ni = 0; ni < 8; ni++)
#pragma unroll
            for (int q = 0; q < 4; q++) acc[mi][ni][q] = 0.f;

#pragma unroll
    for (int k = 0; k < 8; k++) {
        int k0 = k * 16;
        uint32_t afh[2][4], afl[2][4], bfh[8][2], bfl[8][2];
#pragma unroll
        for (int mi = 0; mi < 2; mi++) {
            int r = bm + mi * 16 + lr;
            afh[mi][0] = *(const uint32_t*)&sAh[r * SA + k0 + lc];
            afh[mi][1] = *(const uint32_t*)&sAh[(r + 8) * SA + k0 + lc];
            afh[mi][2] = *(const uint32_t*)&sAh[r * SA + k0 + 8 + lc];
            afh[mi][3] = *(const uint32_t*)&sAh[(r + 8) * SA + k0 + 8 + lc];
            afl[mi][0] = *(const uint32_t*)&sAl[r * SA + k0 + lc];
            afl[mi][1] = *(const uint32_t*)&sAl[(r + 8) * SA + k0 + lc];
            afl[mi][2] = *(const uint32_t*)&sAl[r * SA + k0 + 8 + lc];
            afl[mi][3] = *(const uint32_t*)&sAl[(r + 8) * SA + k0 + 8 + lc];
        }
#pragma unroll
        for (int ni = 0; ni < 8; ni++) {
            int cc = bn + ni * 8 + lr;
            bfh[ni][0] = *(const uint32_t*)&sWh[cc * SA + k0 + lc];
            bfh[ni][1] = *(const uint32_t*)&sWh[cc * SA + k0 + 8 + lc];
            bfl[ni][0] = *(const uint32_t*)&sWl[cc * SA + k0 + lc];
            bfl[ni][1] = *(const uint32_t*)&sWl[cc * SA + k0 + 8 + lc];
        }
#pragma unroll
        for (int mi = 0; mi < 2; mi++)
#pragma unroll
            for (int ni = 0; ni < 8; ni++) {
                mma16816(acc[mi][ni], afh[mi], bfh[ni]);   // hi*hi
                mma16816(acc[mi][ni], afh[mi], bfl[ni]);   // hi*lo
                mma16816(acc[mi][ni], afl[mi], bfh[ni]);   // lo*hi
            }
    }

    float* C = g_h[out_buf];
#pragma unroll
    for (int mi = 0; mi < 2; mi++) {
        int r0 = blockIdx.x * 128 + bm + mi * 16 + lr;
        int r1 = r0 + 8;
        float ps0 = 1.f, ps1 = 1.f;
        if (do_ps) {
            if (r0 < N_NODES) ps0 = g_ns[r0];
            if (r1 < N_NODES) ps1 = g_ns[r1];
        }
#pragma unroll
        for (int ni = 0; ni < 8; ni++) {
            int col = bn + ni * 8 + lc;
            float2 bv = *(const float2*)&b[col];
            if (r0 < N_NODES) {
                float2 o;
                o.x = fmaxf(acc[mi][ni][0] + bv.x, 0.f) * ps0;
                o.y = fmaxf(acc[mi][ni][1] + bv.y, 0.f) * ps0;
                *(float2*)&C[(size_t)r0 * DIM + col] = o;
            }
            if (r1 < N_NODES) {
                float2 o;
                o.x = fmaxf(acc[mi][ni][2] + bv.x, 0.f) * ps1;
                o.y = fmaxf(acc[mi][ni][3] + bv.y, 0.f) * ps1;
                *(float2*)&C[(size_t)r1 * DIM + col] = o;
            }
        }
    }
}

// ---------------- pooling: sorted graph_id -> register accumulation ----------------
__global__ void pool_kernel(int buf, const int* __restrict__ gid) {
    const float* h = g_h[buf];
    int group = blockIdx.x * 2 + (threadIdx.x >> 7);
    int d = threadIdx.x & 127;
    int start = group * 128;
    if (start >= N_NODES) return;
    int end = min(start + 128, N_NODES);

    int cur = gid[start];
    float acc = 0.f;
    int cnt = 0;
    for (int n = start; n < end; n++) {
        int g = gid[n];
        if (g != cur) {
            atomicAdd(&g_pooled[cur * DIM + d], acc);
            if (d == 0) atomicAdd(&g_gcount[cur], cnt);
            acc = 0.f; cnt = 0; cur = g;
        }
        acc += h[n * DIM + d];
        cnt++;
    }
    atomicAdd(&g_pooled[cur * DIM + d], acc);
    if (d == 0) atomicAdd(&g_gcount[cur], cnt);
}

// ---------------- head MLP ----------------
__global__ void mlp_kernel(const float* __restrict__ Wa, const float* __restrict__ ba,
                           const float* __restrict__ Wb, const float* __restrict__ bb,
                           float* __restrict__ out) {
    __shared__ float pm[N_GRAPHS * DIM];
    __shared__ float z[N_GRAPHS * HID];
    int t = threadIdx.x;

    for (int i = t; i < N_GRAPHS * DIM; i += 256) {
        int g = i / DIM;
        float cnt = fmaxf((float)g_gcount[g], 1.0f);
        pm[i] = g_pooled[i] / cnt;
    }
    __syncthreads();

    for (int i = t; i < N_GRAPHS * HID; i += 256) {
        int g = i / HID, j = i % HID;
        float s = ba[j];
        for (int d = 0; d < DIM; d++) s += pm[g * DIM + d] * Wa[d * HID + j];
        z[i] = fmaxf(s, 0.0f);
    }
    __syncthreads();

    for (int i = t; i < N_GRAPHS * N_CLASS; i += 256) {
        int g = i / N_CLASS, c = i % N_CLASS;
        float s = bb[c];
        for (int j = 0; j < HID; j++) s += z[g * HID + j] * Wb[j * N_CLASS + c];
        out[i] = s;
    }
}

// ---------------- launch ----------------
extern "C" void kernel_launch(void* const* d_in, const int* in_sizes, int n_in,
                              void* d_out, int out_size) {
    const float* feat = (const float*)d_in[0];
    const int* src = (const int*)d_in[1];
    const int* dst = (const int*)d_in[2];
    const int* gid = (const int*)d_in[3];
    const float* Ws[6] = {(const float*)d_in[4], (const float*)d_in[6], (const float*)d_in[8],
                          (const float*)d_in[10], (const float*)d_in[12], (const float*)d_in[14]};
    const float* bs[6] = {(const float*)d_in[5], (const float*)d_in[7], (const float*)d_in[9],
                          (const float*)d_in[11], (const float*)d_in[13], (const float*)d_in[15]};
    const float* Wa = (const float*)d_in[16];
    const float* ba = (const float*)d_in[17];
    const float* Wb = (const float*)d_in[18];
    const float* bb = (const float*)d_in[19];
    float* out = (float*)d_out;

    const int SMEM_DYN = 4 * 128 * SA * 2;   // 139264 B
    cudaFuncSetAttribute(gemm_mma, cudaFuncAttributeMaxDynamicSharedMemorySize, SMEM_DYN);

    // graph structure: 4 launches
    setup_kernel<<<384, 256>>>(Ws[0], Ws[1], Ws[2], Ws[3], Ws[4], Ws[5]);
    degree_kernel<<<(N_EDGES + 255) / 256, 256>>>(src, dst);
    scanfull_kernel<<<SCAN_BLOCKS, 256>>>();
    fill_csr<<<(N_EDGES + 255) / 256, 256>>>(src, dst);

    const int AGG_GRID = (N_NODES * 32 + 255) / 256;

    // Layer 0: per-edge src norm. GEMM epilogue pre-scales layers 0..4 by ns,
    // so layers 1..5 aggregate without per-edge norm loads. relu(x)*ns == relu(x*ns).
    aggregate_kernel<1, 1, 1><<<AGG_GRID, 256>>>(feat, -1, nullptr);
    gemm_mma<<<N_TILES, 256, SMEM_DYN>>>(bs[0], 0, 0, 1);

    for (int L = 1; L < 6; L++) {
        aggregate_kernel<0, 1, 1><<<AGG_GRID, 256>>>(nullptr, (L - 1) & 1, nullptr);
        gemm_mma<<<N_TILES, 256, SMEM_DYN>>>(bs[L], L, L & 1, (L < 5) ? 1 : 0);
    }
    // final features in g_h[1]

    pool_kernel<<<SCAN_BLOCKS, 256>>>(1, gid);
    mlp_kernel<<<1, 256>>>(Wa, ba, Wb, bb, out);

    // unnormalized aggregation h_agg [50000,128] (fp32 exact)
    aggregate_kernel<0, 0, 0><<<AGG_GRID, 256>>>(nullptr, 1, out + N_GRAPHS * N_CLASS);
}

// round 12
// speedup vs baseline: 1.0054x; 1.0010x over previous
#include <cuda_runtime.h>
#include <cuda_bf16.h>
#include <cstdint>

#define N_NODES 50000
#define N_EDGES 800000
#define DIM     128
#define N_GRAPHS 64
#define N_CLASS  10
#define HID      64
#define SCAN_BLOCKS 196   // ceil(50000/256)
#define N_TILES 391       // ceil(50000/128)
#define N_PAD   (N_TILES * 128)
#define SA      136       // padded K-stride in smem (bank-conflict-free fragments)

// ---------------- device scratch ----------------
__device__ float g_h[2][N_NODES * DIM];
__device__ unsigned short g_Ahi[N_PAD * DIM];   // row-major bf16 hi of aggregated feats
__device__ unsigned short g_Alo[N_PAD * DIM];   // row-major bf16 lo
__device__ unsigned short g_Whi[6 * DIM * DIM]; // row-major W^T [N][K] bf16 hi
__device__ unsigned short g_Wlo[6 * DIM * DIM];
__device__ float g_ns[N_NODES];
__device__ float g_nd[N_NODES];
__device__ int   g_indeg[N_NODES];
__device__ int   g_outdeg[N_NODES];
__device__ int   g_rowptr[N_NODES + 1];
__device__ int   g_cursor[N_NODES];   // initialized to rowptr by scanfull_kernel
__device__ int   g_csrsrc[N_EDGES];
__device__ float g_pooled[N_GRAPHS * DIM];
__device__ int   g_gcount[N_GRAPHS];

__device__ __forceinline__ void split_bf(float x, unsigned short& hi, unsigned short& lo) {
    __nv_bfloat16 h = __float2bfloat16_rn(x);
    hi = __bfloat16_as_ushort(h);
    lo = __bfloat16_as_ushort(__float2bfloat16_rn(x - __bfloat162float(h)));
}

__device__ __forceinline__ void mma16816(float* c, const uint32_t* a, const uint32_t* b) {
    asm volatile(
        "mma.sync.aligned.m16n8k16.row.col.f32.bf16.bf16.f32 "
        "{%0,%1,%2,%3}, {%4,%5,%6,%7}, {%8,%9}, {%0,%1,%2,%3};"
        : "+f"(c[0]), "+f"(c[1]), "+f"(c[2]), "+f"(c[3])
        : "r"(a[0]), "r"(a[1]), "r"(a[2]), "r"(a[3]), "r"(b[0]), "r"(b[1]));
}

// ---------------- setup: zero counters + tail tiles + weight conversion (one launch) ----------------
__global__ void setup_kernel(const float* W0, const float* W1, const float* W2,
                             const float* W3, const float* W4, const float* W5) {
    int idx = blockIdx.x * 256 + threadIdx.x;
    if (idx < N_NODES) { g_indeg[idx] = 0; g_outdeg[idx] = 0; }
    if (idx < N_GRAPHS * DIM) g_pooled[idx] = 0.0f;
    if (idx < N_GRAPHS) g_gcount[idx] = 0;
    if (idx < 768) ((uint4*)(g_Ahi + N_NODES * DIM))[idx] = make_uint4(0, 0, 0, 0);
    else if (idx < 1536) ((uint4*)(g_Alo + N_NODES * DIM))[idx - 768] = make_uint4(0, 0, 0, 0);

    int layer = idx >> 14;
    int r = idx & 16383;
    int n = r >> 7, k = r & 127;
    const float* Ws[6] = {W0, W1, W2, W3, W4, W5};
    float val = Ws[layer][k * DIM + n];
    unsigned short hi, lo;
    split_bf(val, hi, lo);
    g_Whi[idx] = hi;
    g_Wlo[idx] = lo;
}

__global__ void degree_kernel(const int* __restrict__ src, const int* __restrict__ dst) {
    int e = blockIdx.x * blockDim.x + threadIdx.x;
    if (e < N_EDGES) {
        atomicAdd(&g_outdeg[src[e]], 1);
        atomicAdd(&g_indeg[dst[e]], 1);
    }
}

// ---------------- norm + full exclusive scan of indeg -> rowptr (+cursor init), ONE launch ----------------
__global__ void scanfull_kernel() {
    __shared__ int ws[8];
    __shared__ int s[256];
    __shared__ int boff_sh;
    int t = threadIdx.x;
    int base = blockIdx.x * 256;
    int i = base + t;

    if (i < N_NODES) {
        g_ns[i] = rsqrtf((float)max(g_outdeg[i], 1));
        g_nd[i] = rsqrtf((float)max(g_indeg[i], 1));
    }

    int part = 0;
    for (int j = t; j < base; j += 256) part += g_indeg[j];
#pragma unroll
    for (int o = 16; o; o >>= 1) part += __shfl_down_sync(0xffffffffu, part, o);
    if ((t & 31) == 0) ws[t >> 5] = part;

    int v = (i < N_NODES) ? g_indeg[i] : 0;
    s[t] = v;
    __syncthreads();
    if (t == 0) {
        int b = 0;
#pragma unroll
        for (int w = 0; w < 8; w++) b += ws[w];
        boff_sh = b;
    }
    __syncthreads();
    int boff = boff_sh;

    for (int o = 1; o < 256; o <<= 1) {
        int x = (t >= o) ? s[t - o] : 0;
        __syncthreads();
        s[t] += x;
        __syncthreads();
    }
    if (i < N_NODES) {
        int r = boff + s[t] - v;
        g_rowptr[i] = r;
        g_cursor[i] = r;   // cursor starts at row offset -> fill_csr needs no rowptr load
        if (i == N_NODES - 1) g_rowptr[N_NODES] = r + v;
    }
}

// ---------------- CSR fill: cursor IS the slot ----------------
__global__ void fill_csr(const int* __restrict__ src, const int* __restrict__ dst) {
    int e = blockIdx.x * blockDim.x + threadIdx.x;
    if (e < N_EDGES) {
        int slot = atomicAdd(&g_cursor[dst[e]], 1);
        g_csrsrc[slot] = src[e];
    }
}

// ---------------- aggregation: one warp per destination node, 4x unrolled ----------------
template <int SRC_NORM, int DST_NORM, int OUT_BF16>
__global__ void aggregate_kernel(const float* __restrict__ ext_in, int in_sel,
                                 float* __restrict__ ext_out) {
    const float* hin = (in_sel == 0) ? g_h[0] : (in_sel == 1) ? g_h[1] : ext_in;

    int v = (blockIdx.x * blockDim.x + threadIdx.x) >> 5;
    if (v >= N_NODES) return;
    int lane = threadIdx.x & 31;

    int beg = g_rowptr[v];
    int end = g_rowptr[v + 1];

    const float4* h4 = (const float4*)hin;
    float4 acc = make_float4(0.f, 0.f, 0.f, 0.f);

    int i = beg;
    for (; i + 4 <= end; i += 4) {
        int s0 = g_csrsrc[i + 0];
        int s1 = g_csrsrc[i + 1];
        int s2 = g_csrsrc[i + 2];
        int s3 = g_csrsrc[i + 3];
        float w0 = SRC_NORM ? g_ns[s0] : 1.0f;
        float w1 = SRC_NORM ? g_ns[s1] : 1.0f;
        float w2 = SRC_NORM ? g_ns[s2] : 1.0f;
        float w3 = SRC_NORM ? g_ns[s3] : 1.0f;
        float4 v0 = h4[s0 * 32 + lane];
        float4 v1 = h4[s1 * 32 + lane];
        float4 v2 = h4[s2 * 32 + lane];
        float4 v3 = h4[s3 * 32 + lane];
        acc.x += w0 * v0.x; acc.y += w0 * v0.y; acc.z += w0 * v0.z; acc.w += w0 * v0.w;
        acc.x += w1 * v1.x; acc.y += w1 * v1.y; acc.z += w1 * v1.z; acc.w += w1 * v1.w;
        acc.x += w2 * v2.x; acc.y += w2 * v2.y; acc.z += w2 * v2.z; acc.w += w2 * v2.w;
        acc.x += w3 * v3.x; acc.y += w3 * v3.y; acc.z += w3 * v3.z; acc.w += w3 * v3.w;
    }
    for (; i < end; i++) {
        int s = g_csrsrc[i];
        float w = SRC_NORM ? g_ns[s] : 1.0f;
        float4 vv = h4[s * 32 + lane];
        acc.x += w * vv.x; acc.y += w * vv.y; acc.z += w * vv.z; acc.w += w * vv.w;
    }
    if (DST_NORM) {
        float sc = g_nd[v];
        acc.x *= sc; acc.y *= sc; acc.z *= sc; acc.w *= sc;
    }

    if (OUT_BF16) {
        unsigned short h0, h1, h2, h3, l0, l1, l2, l3;
        split_bf(acc.x, h0, l0); split_bf(acc.y, h1, l1);
        split_bf(acc.z, h2, l2); split_bf(acc.w, h3, l3);
        uint2 hv = make_uint2((uint32_t)h0 | ((uint32_t)h1 << 16),
                              (uint32_t)h2 | ((uint32_t)h3 << 16));
        uint2 lv = make_uint2((uint32_t)l0 | ((uint32_t)l1 << 16),
                              (uint32_t)l2 | ((uint32_t)l3 << 16));
        *(uint2*)&g_Ahi[(size_t)v * DIM + lane * 4] = hv;
        *(uint2*)&g_Alo[(size_t)v * DIM + lane * 4] = lv;
    } else {
        ((float4*)ext_out)[v * 32 + lane] = acc;
    }
}

// ---------------- tensor-core GEMM via mma.sync (bf16x2 split, fused passes) ----------------
// 512 threads = 16 warps (4M x 4N), warp tile 32x32 -> 4 warps/SMSP for latency hiding.
// g_h[out_buf][row] = relu(A[row] @ W + b) * (do_ps ? g_ns[row] : 1)
__global__ void __launch_bounds__(512, 1) gemm_mma(
    const float* __restrict__ b, int layer, int out_buf, int do_ps) {
    extern __shared__ __align__(16) unsigned short sm[];
    unsigned short* sAh = sm;
    unsigned short* sAl = sm + 128 * SA;
    unsigned short* sWh = sm + 2 * 128 * SA;
    unsigned short* sWl = sm + 3 * 128 * SA;

    int tid = threadIdx.x;
    const uint4* gAh = (const uint4*)(g_Ahi + (size_t)blockIdx.x * (128 * DIM));
    const uint4* gAl = (const uint4*)(g_Alo + (size_t)blockIdx.x * (128 * DIM));
    const uint4* gWh = (const uint4*)(g_Whi + (size_t)layer * (DIM * DIM));
    const uint4* gWl = (const uint4*)(g_Wlo + (size_t)layer * (DIM * DIM));

    // stage tiles: 2048 uint4 each, 512 threads -> 4 per thread per buffer
#pragma unroll
    for (int it = 0; it < 4; it++) {
        int i = tid + it * 512;
        int r = i >> 4, c = (i & 15) << 3;
        *(uint4*)&sAh[r * SA + c] = gAh[i];
        *(uint4*)&sAl[r * SA + c] = gAl[i];
        *(uint4*)&sWh[r * SA + c] = gWh[i];
        *(uint4*)&sWl[r * SA + c] = gWl[i];
    }
    __syncthreads();

    int warp = tid >> 5, lane = tid & 31;
    int wm = warp & 3, wn = warp >> 2;           // 4 M-warps x 4 N-warps
    int bm = wm * 32, bn = wn * 32;
    int lr = lane >> 2, lc = (lane & 3) * 2;

    float acc[2][4][4];
#pragma unroll
    for (int mi = 0; mi < 2; mi++)
#pragma unroll
        for (int ni = 0; ni < 4; ni++)
#pragma unroll
            for (int q = 0; q < 4; q++) acc[mi][ni][q] = 0.f;

#pragma unroll
    for (int k = 0; k < 8; k++) {
        int k0 = k * 16;
        uint32_t afh[2][4], afl[2][4], bfh[4][2], bfl[4][2];
#pragma unroll
        for (int mi = 0; mi < 2; mi++) {
            int r = bm + mi * 16 + lr;
            afh[mi][0] = *(const uint32_t*)&sAh[r * SA + k0 + lc];
            afh[mi][1] = *(const uint32_t*)&sAh[(r + 8) * SA + k0 + lc];
            afh[mi][2] = *(const uint32_t*)&sAh[r * SA + k0 + 8 + lc];
            afh[mi][3] = *(const uint32_t*)&sAh[(r + 8) * SA + k0 + 8 + lc];
            afl[mi][0] = *(const uint32_t*)&sAl[r * SA + k0 + lc];
            afl[mi][1] = *(const uint32_t*)&sAl[(r + 8) * SA + k0 + lc];
            afl[mi][2] = *(const uint32_t*)&sAl[r * SA + k0 + 8 + lc];
            afl[mi][3] = *(const uint32_t*)&sAl[(r + 8) * SA + k0 + 8 + lc];
        }
#pragma unroll
        for (int ni = 0; ni < 4; ni++) {
            int cc = bn + ni * 8 + lr;
            bfh[ni][0] = *(const uint32_t*)&sWh[cc * SA + k0 + lc];
            bfh[ni][1] = *(const uint32_t*)&sWh[cc * SA + k0 + 8 + lc];
            bfl[ni][0] = *(const uint32_t*)&sWl[cc * SA + k0 + lc];
            bfl[ni][1] = *(const uint32_t*)&sWl[cc * SA + k0 + 8 + lc];
        }
#pragma unroll
        for (int mi = 0; mi < 2; mi++)
#pragma unroll
            for (int ni = 0; ni < 4; ni++) {
                mma16816(acc[mi][ni], afh[mi], bfh[ni]);   // hi*hi
                mma16816(acc[mi][ni], afh[mi], bfl[ni]);   // hi*lo
                mma16816(acc[mi][ni], afl[mi], bfh[ni]);   // lo*hi
            }
    }

    float* C = g_h[out_buf];
#pragma unroll
    for (int mi = 0; mi < 2; mi++) {
        int r0 = blockIdx.x * 128 + bm + mi * 16 + lr;
        int r1 = r0 + 8;
        float ps0 = 1.f, ps1 = 1.f;
        if (do_ps) {
            if (r0 < N_NODES) ps0 = g_ns[r0];
            if (r1 < N_NODES) ps1 = g_ns[r1];
        }
#pragma unroll
        for (int ni = 0; ni < 4; ni++) {
            int col = bn + ni * 8 + lc;
            float2 bv = *(const float2*)&b[col];
            if (r0 < N_NODES) {
                float2 o;
                o.x = fmaxf(acc[mi][ni][0] + bv.x, 0.f) * ps0;
                o.y = fmaxf(acc[mi][ni][1] + bv.y, 0.f) * ps0;
                *(float2*)&C[(size_t)r0 * DIM + col] = o;
            }
            if (r1 < N_NODES) {
                float2 o;
                o.x = fmaxf(acc[mi][ni][2] + bv.x, 0.f) * ps1;
                o.y = fmaxf(acc[mi][ni][3] + bv.y, 0.f) * ps1;
                *(float2*)&C[(size_t)r1 * DIM + col] = o;
            }
        }
    }
}

// ---------------- pooling: sorted graph_id -> register accumulation ----------------
__global__ void pool_kernel(int buf, const int* __restrict__ gid) {
    const float* h = g_h[buf];
    int group = blockIdx.x * 2 + (threadIdx.x >> 7);
    int d = threadIdx.x & 127;
    int start = group * 128;
    if (start >= N_NODES) return;
    int end = min(start + 128, N_NODES);

    int cur = gid[start];
    float acc = 0.f;
    int cnt = 0;
    for (int n = start; n < end; n++) {
        int g = gid[n];
        if (g != cur) {
            atomicAdd(&g_pooled[cur * DIM + d], acc);
            if (d == 0) atomicAdd(&g_gcount[cur], cnt);
            acc = 0.f; cnt = 0; cur = g;
        }
        acc += h[n * DIM + d];
        cnt++;
    }
    atomicAdd(&g_pooled[cur * DIM + d], acc);
    if (d == 0) atomicAdd(&g_gcount[cur], cnt);
}

// ---------------- head MLP ----------------
__global__ void mlp_kernel(const float* __restrict__ Wa, const float* __restrict__ ba,
                           const float* __restrict__ Wb, const float* __restrict__ bb,
                           float* __restrict__ out) {
    __shared__ float pm[N_GRAPHS * DIM];
    __shared__ float z[N_GRAPHS * HID];
    int t = threadIdx.x;

    for (int i = t; i < N_GRAPHS * DIM; i += 256) {
        int g = i / DIM;
        float cnt = fmaxf((float)g_gcount[g], 1.0f);
        pm[i] = g_pooled[i] / cnt;
    }
    __syncthreads();

    for (int i = t; i < N_GRAPHS * HID; i += 256) {
        int g = i / HID, j = i % HID;
        float s = ba[j];
        for (int d = 0; d < DIM; d++) s += pm[g * DIM + d] * Wa[d * HID + j];
        z[i] = fmaxf(s, 0.0f);
    }
    __syncthreads();

    for (int i = t; i < N_GRAPHS * N_CLASS; i += 256) {
        int g = i / N_CLASS, c = i % N_CLASS;
        float s = bb[c];
        for (int j = 0; j < HID; j++) s += z[g * HID + j] * Wb[j * N_CLASS + c];
        out[i] = s;
    }
}

// ---------------- launch ----------------
extern "C" void kernel_launch(void* const* d_in, const int* in_sizes, int n_in,
                              void* d_out, int out_size) {
    const float* feat = (const float*)d_in[0];
    const int* src = (const int*)d_in[1];
    const int* dst = (const int*)d_in[2];
    const int* gid = (const int*)d_in[3];
    const float* Ws[6] = {(const float*)d_in[4], (const float*)d_in[6], (const float*)d_in[8],
                          (const float*)d_in[10], (const float*)d_in[12], (const float*)d_in[14]};
    const float* bs[6] = {(const float*)d_in[5], (const float*)d_in[7], (const float*)d_in[9],
                          (const float*)d_in[11], (const float*)d_in[13], (const float*)d_in[15]};
    const float* Wa = (const float*)d_in[16];
    const float* ba = (const float*)d_in[17];
    const float* Wb = (const float*)d_in[18];
    const float* bb = (const float*)d_in[19];
    float* out = (float*)d_out;

    const int SMEM_DYN = 4 * 128 * SA * 2;   // 139264 B
    cudaFuncSetAttribute(gemm_mma, cudaFuncAttributeMaxDynamicSharedMemorySize, SMEM_DYN);

    // graph structure: 4 launches
    setup_kernel<<<384, 256>>>(Ws[0], Ws[1], Ws[2], Ws[3], Ws[4], Ws[5]);
    degree_kernel<<<(N_EDGES + 255) / 256, 256>>>(src, dst);
    scanfull_kernel<<<SCAN_BLOCKS, 256>>>();
    fill_csr<<<(N_EDGES + 255) / 256, 256>>>(src, dst);

    const int AGG_GRID = (N_NODES * 32 + 255) / 256;

    // Layer 0: per-edge src norm. GEMM epilogue pre-scales layers 0..4 by ns,
    // so layers 1..5 aggregate without per-edge norm loads. relu(x)*ns == relu(x*ns).
    aggregate_kernel<1, 1, 1><<<AGG_GRID, 256>>>(feat, -1, nullptr);
    gemm_mma<<<N_TILES, 512, SMEM_DYN>>>(bs[0], 0, 0, 1);

    for (int L = 1; L < 6; L++) {
        aggregate_kernel<0, 1, 1><<<AGG_GRID, 256>>>(nullptr, (L - 1) & 1, nullptr);
        gemm_mma<<<N_TILES, 512, SMEM_DYN>>>(bs[L], L, L & 1, (L < 5) ? 1 : 0);
    }
    // final features in g_h[1]

    pool_kernel<<<SCAN_BLOCKS, 256>>>(1, gid);
    mlp_kernel<<<1, 256>>>(Wa, ba, Wb, bb, out);

    // unnormalized aggregation h_agg [50000,128] (fp32 exact)
    aggregate_kernel<0, 0, 0><<<AGG_GRID, 256>>>(nullptr, 1, out + N_GRAPHS * N_CLASS);
}

// round 13
// speedup vs baseline: 1.1017x; 1.0958x over previous
#include <cuda_runtime.h>
#include <cuda_bf16.h>
#include <cuda_fp16.h>
#include <cstdint>

#define N_NODES 50000
#define N_EDGES 800000
#define DIM     128
#define N_GRAPHS 64
#define N_CLASS  10
#define HID      64
#define SCAN_BLOCKS 196   // ceil(50000/256)
#define N_TILES 391       // ceil(50000/128)
#define N_PAD   (N_TILES * 128)
#define SA      136       // padded K-stride in smem (bank-conflict-free fragments)

// ---------------- device scratch ----------------
__device__ __half g_h16[2][N_NODES * DIM];      // fp16 node features (ping-pong)
__device__ __half g_feat16[N_NODES * DIM];      // fp16 copy of input features
__device__ unsigned short g_Ahi[N_PAD * DIM];   // row-major bf16 hi of aggregated feats
__device__ unsigned short g_Alo[N_PAD * DIM];   // row-major bf16 lo
__device__ unsigned short g_Whi[6 * DIM * DIM]; // row-major W^T [N][K] bf16 hi
__device__ unsigned short g_Wlo[6 * DIM * DIM];
__device__ float g_ns[N_NODES];
__device__ float g_nd[N_NODES];
__device__ int   g_indeg[N_NODES];
__device__ int   g_outdeg[N_NODES];
__device__ int   g_rowptr[N_NODES + 1];
__device__ int   g_cursor[N_NODES];   // initialized to rowptr by scanfull_kernel
__device__ int   g_csrsrc[N_EDGES];
__device__ float g_pooled[N_GRAPHS * DIM];
__device__ int   g_gcount[N_GRAPHS];

__device__ __forceinline__ void split_bf(float x, unsigned short& hi, unsigned short& lo) {
    __nv_bfloat16 h = __float2bfloat16_rn(x);
    hi = __bfloat16_as_ushort(h);
    lo = __bfloat16_as_ushort(__float2bfloat16_rn(x - __bfloat162float(h)));
}

__device__ __forceinline__ void mma16816(float* c, const uint32_t* a, const uint32_t* b) {
    asm volatile(
        "mma.sync.aligned.m16n8k16.row.col.f32.bf16.bf16.f32 "
        "{%0,%1,%2,%3}, {%4,%5,%6,%7}, {%8,%9}, {%0,%1,%2,%3};"
        : "+f"(c[0]), "+f"(c[1]), "+f"(c[2]), "+f"(c[3])
        : "r"(a[0]), "r"(a[1]), "r"(a[2]), "r"(a[3]), "r"(b[0]), "r"(b[1]));
}

// ---------------- setup: feat->fp16, zero counters, tail tiles, weight conversion ----------------
// grid = 6250 blocks x 256 = 1.6M threads (one float4 of feat each)
__global__ void setup_kernel(const float* __restrict__ feat,
                             const float* W0, const float* W1, const float* W2,
                             const float* W3, const float* W4, const float* W5) {
    int idx = blockIdx.x * 256 + threadIdx.x;

    // feat fp32 -> fp16 (float4 -> 2x half2)
    {
        float4 f = ((const float4*)feat)[idx];   // idx < 1.6M always (grid sized exactly)
        __half2 h01 = __floats2half2_rn(f.x, f.y);
        __half2 h23 = __floats2half2_rn(f.z, f.w);
        uint2 packed = make_uint2(*(uint32_t*)&h01, *(uint32_t*)&h23);
        ((uint2*)g_feat16)[idx] = packed;
    }

    if (idx < N_NODES) { g_indeg[idx] = 0; g_outdeg[idx] = 0; }
    if (idx < N_GRAPHS * DIM) g_pooled[idx] = 0.0f;
    if (idx < N_GRAPHS) g_gcount[idx] = 0;
    if (idx < 768) ((uint4*)(g_Ahi + N_NODES * DIM))[idx] = make_uint4(0, 0, 0, 0);
    else if (idx < 1536) ((uint4*)(g_Alo + N_NODES * DIM))[idx - 768] = make_uint4(0, 0, 0, 0);

    if (idx < 6 * DIM * DIM) {
        int layer = idx >> 14;
        int r = idx & 16383;
        int n = r >> 7, k = r & 127;
        const float* Ws[6] = {W0, W1, W2, W3, W4, W5};
        float val = Ws[layer][k * DIM + n];
        unsigned short hi, lo;
        split_bf(val, hi, lo);
        g_Whi[idx] = hi;
        g_Wlo[idx] = lo;
    }
}

__global__ void degree_kernel(const int* __restrict__ src, const int* __restrict__ dst) {
    int e = blockIdx.x * blockDim.x + threadIdx.x;
    if (e < N_EDGES) {
        atomicAdd(&g_outdeg[src[e]], 1);
        atomicAdd(&g_indeg[dst[e]], 1);
    }
}

// ---------------- norm + full exclusive scan of indeg -> rowptr (+cursor init), ONE launch ----------------
__global__ void scanfull_kernel() {
    __shared__ int ws[8];
    __shared__ int s[256];
    __shared__ int boff_sh;
    int t = threadIdx.x;
    int base = blockIdx.x * 256;
    int i = base + t;

    if (i < N_NODES) {
        g_ns[i] = rsqrtf((float)max(g_outdeg[i], 1));
        g_nd[i] = rsqrtf((float)max(g_indeg[i], 1));
    }

    int part = 0;
    for (int j = t; j < base; j += 256) part += g_indeg[j];
#pragma unroll
    for (int o = 16; o; o >>= 1) part += __shfl_down_sync(0xffffffffu, part, o);
    if ((t & 31) == 0) ws[t >> 5] = part;

    int v = (i < N_NODES) ? g_indeg[i] : 0;
    s[t] = v;
    __syncthreads();
    if (t == 0) {
        int b = 0;
#pragma unroll
        for (int w = 0; w < 8; w++) b += ws[w];
        boff_sh = b;
    }
    __syncthreads();
    int boff = boff_sh;

    for (int o = 1; o < 256; o <<= 1) {
        int x = (t >= o) ? s[t - o] : 0;
        __syncthreads();
        s[t] += x;
        __syncthreads();
    }
    if (i < N_NODES) {
        int r = boff + s[t] - v;
        g_rowptr[i] = r;
        g_cursor[i] = r;
        if (i == N_NODES - 1) g_rowptr[N_NODES] = r + v;
    }
}

// ---------------- CSR fill: cursor IS the slot ----------------
__global__ void fill_csr(const int* __restrict__ src, const int* __restrict__ dst) {
    int e = blockIdx.x * blockDim.x + threadIdx.x;
    if (e < N_EDGES) {
        int slot = atomicAdd(&g_cursor[dst[e]], 1);
        g_csrsrc[slot] = src[e];
    }
}

// ---------------- aggregation: fp16 input, one warp per dst node, 4x unrolled ----------------
// in_sel: 0/1 -> g_h16[sel], 2 -> g_feat16
// OUT_BF16=1: write bf16 hi/lo row-major (GEMM input). Else fp32 to ext_out.
template <int SRC_NORM, int DST_NORM, int OUT_BF16>
__global__ void aggregate_kernel(int in_sel, float* __restrict__ ext_out) {
    const __half* hin = (in_sel == 0) ? g_h16[0] : (in_sel == 1) ? g_h16[1] : g_feat16;

    int v = (blockIdx.x * blockDim.x + threadIdx.x) >> 5;
    if (v >= N_NODES) return;
    int lane = threadIdx.x & 31;

    int beg = g_rowptr[v];
    int end = g_rowptr[v + 1];

    const uint2* h2 = (const uint2*)hin;   // 4 halves per uint2; row = 32 uint2
    float4 acc = make_float4(0.f, 0.f, 0.f, 0.f);

    int i = beg;
    for (; i + 4 <= end; i += 4) {
        int s0 = g_csrsrc[i + 0];
        int s1 = g_csrsrc[i + 1];
        int s2 = g_csrsrc[i + 2];
        int s3 = g_csrsrc[i + 3];
        float w0 = SRC_NORM ? g_ns[s0] : 1.0f;
        float w1 = SRC_NORM ? g_ns[s1] : 1.0f;
        float w2 = SRC_NORM ? g_ns[s2] : 1.0f;
        float w3 = SRC_NORM ? g_ns[s3] : 1.0f;
        uint2 r0 = h2[s0 * 32 + lane];
        uint2 r1 = h2[s1 * 32 + lane];
        uint2 r2 = h2[s2 * 32 + lane];
        uint2 r3 = h2[s3 * 32 + lane];
        float2 a0 = __half22float2(*(__half2*)&r0.x), b0 = __half22float2(*(__half2*)&r0.y);
        float2 a1 = __half22float2(*(__half2*)&r1.x), b1 = __half22float2(*(__half2*)&r1.y);
        float2 a2 = __half22float2(*(__half2*)&r2.x), b2 = __half22float2(*(__half2*)&r2.y);
        float2 a3 = __half22float2(*(__half2*)&r3.x), b3 = __half22float2(*(__half2*)&r3.y);
        acc.x += w0 * a0.x; acc.y += w0 * a0.y; acc.z += w0 * b0.x; acc.w += w0 * b0.y;
        acc.x += w1 * a1.x; acc.y += w1 * a1.y; acc.z += w1 * b1.x; acc.w += w1 * b1.y;
        acc.x += w2 * a2.x; acc.y += w2 * a2.y; acc.z += w2 * b2.x; acc.w += w2 * b2.y;
        acc.x += w3 * a3.x; acc.y += w3 * a3.y; acc.z += w3 * b3.x; acc.w += w3 * b3.y;
    }
    for (; i < end; i++) {
        int s = g_csrsrc[i];
        float w = SRC_NORM ? g_ns[s] : 1.0f;
        uint2 rr = h2[s * 32 + lane];
        float2 aa = __half22float2(*(__half2*)&rr.x), bb = __half22float2(*(__half2*)&rr.y);
        acc.x += w * aa.x; acc.y += w * aa.y; acc.z += w * bb.x; acc.w += w * bb.y;
    }
    if (DST_NORM) {
        float sc = g_nd[v];
        acc.x *= sc; acc.y *= sc; acc.z *= sc; acc.w *= sc;
    }

    if (OUT_BF16) {
        unsigned short h0, h1, h2s, h3, l0, l1, l2, l3;
        split_bf(acc.x, h0, l0); split_bf(acc.y, h1, l1);
        split_bf(acc.z, h2s, l2); split_bf(acc.w, h3, l3);
        uint2 hv = make_uint2((uint32_t)h0 | ((uint32_t)h1 << 16),
                              (uint32_t)h2s | ((uint32_t)h3 << 16));
        uint2 lv = make_uint2((uint32_t)l0 | ((uint32_t)l1 << 16),
                              (uint32_t)l2 | ((uint32_t)l3 << 16));
        *(uint2*)&g_Ahi[(size_t)v * DIM + lane * 4] = hv;
        *(uint2*)&g_Alo[(size_t)v * DIM + lane * 4] = lv;
    } else {
        ((float4*)ext_out)[v * 32 + lane] = acc;
    }
}

// ---------------- tensor-core GEMM via mma.sync (bf16x2 split, fused passes) ----------------
// 512 threads = 16 warps (4M x 4N), warp tile 32x32.
// g_h16[out_buf][row] = fp16( relu(A[row] @ W + b) * (do_ps ? g_ns[row] : 1) )
__global__ void __launch_bounds__(512, 1) gemm_mma(
    const float* __restrict__ b, int layer, int out_buf, int do_ps) {
    extern __shared__ __align__(16) unsigned short sm[];
    unsigned short* sAh = sm;
    unsigned short* sAl = sm + 128 * SA;
    unsigned short* sWh = sm + 2 * 128 * SA;
    unsigned short* sWl = sm + 3 * 128 * SA;

    int tid = threadIdx.x;
    const uint4* gAh = (const uint4*)(g_Ahi + (size_t)blockIdx.x * (128 * DIM));
    const uint4* gAl = (const uint4*)(g_Alo + (size_t)blockIdx.x * (128 * DIM));
    const uint4* gWh = (const uint4*)(g_Whi + (size_t)layer * (DIM * DIM));
    const uint4* gWl = (const uint4*)(g_Wlo + (size_t)layer * (DIM * DIM));

#pragma unroll
    for (int it = 0; it < 4; it++) {
        int i = tid + it * 512;
        int r = i >> 4, c = (i & 15) << 3;
        *(uint4*)&sAh[r * SA + c] = gAh[i];
        *(uint4*)&sAl[r * SA + c] = gAl[i];
        *(uint4*)&sWh[r * SA + c] = gWh[i];
        *(uint4*)&sWl[r * SA + c] = gWl[i];
    }
    __syncthreads();

    int warp = tid >> 5, lane = tid & 31;
    int wm = warp & 3, wn = warp >> 2;           // 4 M-warps x 4 N-warps
    int bm = wm * 32, bn = wn * 32;
    int lr = lane >> 2, lc = (lane & 3) * 2;

    float acc[2][4][4];
#pragma unroll
    for (int mi = 0; mi < 2; mi++)
#pragma unroll
        for (int ni = 0; ni < 4; ni++)
#pragma unroll
            for (int q = 0; q < 4; q++) acc[mi][ni][q] = 0.f;

#pragma unroll
    for (int k = 0; k < 8; k++) {
        int k0 = k * 16;
        uint32_t afh[2][4], afl[2][4], bfh[4][2], bfl[4][2];
#pragma unroll
        for (int mi = 0; mi < 2; mi++) {
            int r = bm + mi * 16 + lr;
            afh[mi][0] = *(const uint32_t*)&sAh[r * SA + k0 + lc];
            afh[mi][1] = *(const uint32_t*)&sAh[(r + 8) * SA + k0 + lc];
            afh[mi][2] = *(const uint32_t*)&sAh[r * SA + k0 + 8 + lc];
            afh[mi][3] = *(const uint32_t*)&sAh[(r + 8) * SA + k0 + 8 + lc];
            afl[mi][0] = *(const uint32_t*)&sAl[r * SA + k0 + lc];
            afl[mi][1] = *(const uint32_t*)&sAl[(r + 8) * SA + k0 + lc];
            afl[mi][2] = *(const uint32_t*)&sAl[r * SA + k0 + 8 + lc];
            afl[mi][3] = *(const uint32_t*)&sAl[(r + 8) * SA + k0 + 8 + lc];
        }
#pragma unroll
        for (int ni = 0; ni < 4; ni++) {
            int cc = bn + ni * 8 + lr;
            bfh[ni][0] = *(const uint32_t*)&sWh[cc * SA + k0 + lc];
            bfh[ni][1] = *(const uint32_t*)&sWh[cc * SA + k0 + 8 + lc];
            bfl[ni][0] = *(const uint32_t*)&sWl[cc * SA + k0 + lc];
            bfl[ni][1] = *(const uint32_t*)&sWl[cc * SA + k0 + 8 + lc];
        }
#pragma unroll
        for (int mi = 0; mi < 2; mi++)
#pragma unroll
            for (int ni = 0; ni < 4; ni++) {
                mma16816(acc[mi][ni], afh[mi], bfh[ni]);   // hi*hi
                mma16816(acc[mi][ni], afh[mi], bfl[ni]);   // hi*lo
                mma16816(acc[mi][ni], afl[mi], bfh[ni]);   // lo*hi
            }
    }

    __half* C = g_h16[out_buf];
#pragma unroll
    for (int mi = 0; mi < 2; mi++) {
        int r0 = blockIdx.x * 128 + bm + mi * 16 + lr;
        int r1 = r0 + 8;
        float ps0 = 1.f, ps1 = 1.f;
        if (do_ps) {
            if (r0 < N_NODES) ps0 = g_ns[r0];
            if (r1 < N_NODES) ps1 = g_ns[r1];
        }
#pragma unroll
        for (int ni = 0; ni < 4; ni++) {
            int col = bn + ni * 8 + lc;
            float2 bv = *(const float2*)&b[col];
            if (r0 < N_NODES) {
                float ox = fmaxf(acc[mi][ni][0] + bv.x, 0.f) * ps0;
                float oy = fmaxf(acc[mi][ni][1] + bv.y, 0.f) * ps0;
                *(__half2*)&C[(size_t)r0 * DIM + col] = __floats2half2_rn(ox, oy);
            }
            if (r1 < N_NODES) {
                float ox = fmaxf(acc[mi][ni][2] + bv.x, 0.f) * ps1;
                float oy = fmaxf(acc[mi][ni][3] + bv.y, 0.f) * ps1;
                *(__half2*)&C[(size_t)r1 * DIM + col] = __floats2half2_rn(ox, oy);
            }
        }
    }
}

// ---------------- pooling: sorted graph_id -> register accumulation ----------------
__global__ void pool_kernel(int buf, const int* __restrict__ gid) {
    const __half* h = g_h16[buf];
    int group = blockIdx.x * 2 + (threadIdx.x >> 7);
    int d = threadIdx.x & 127;
    int start = group * 128;
    if (start >= N_NODES) return;
    int end = min(start + 128, N_NODES);

    int cur = gid[start];
    float acc = 0.f;
    int cnt = 0;
    for (int n = start; n < end; n++) {
        int g = gid[n];
        if (g != cur) {
            atomicAdd(&g_pooled[cur * DIM + d], acc);
            if (d == 0) atomicAdd(&g_gcount[cur], cnt);
            acc = 0.f; cnt = 0; cur = g;
        }
        acc += __half2float(h[n * DIM + d]);
        cnt++;
    }
    atomicAdd(&g_pooled[cur * DIM + d], acc);
    if (d == 0) atomicAdd(&g_gcount[cur], cnt);
}

// ---------------- head MLP ----------------
__global__ void mlp_kernel(const float* __restrict__ Wa, const float* __restrict__ ba,
                           const float* __restrict__ Wb, const float* __restrict__ bb,
                           float* __restrict__ out) {
    __shared__ float pm[N_GRAPHS * DIM];
    __shared__ float z[N_GRAPHS * HID];
    int t = threadIdx.x;

    for (int i = t; i < N_GRAPHS * DIM; i += 256) {
        int g = i / DIM;
        float cnt = fmaxf((float)g_gcount[g], 1.0f);
        pm[i] = g_pooled[i] / cnt;
    }
    __syncthreads();

    for (int i = t; i < N_GRAPHS * HID; i += 256) {
        int g = i / HID, j = i % HID;
        float s = ba[j];
        for (int d = 0; d < DIM; d++) s += pm[g * DIM + d] * Wa[d * HID + j];
        z[i] = fmaxf(s, 0.0f);
    }
    __syncthreads();

    for (int i = t; i < N_GRAPHS * N_CLASS; i += 256) {
        int g = i / N_CLASS, c = i % N_CLASS;
        float s = bb[c];
        for (int j = 0; j < HID; j++) s += z[g * HID + j] * Wb[j * N_CLASS + c];
        out[i] = s;
    }
}

// ---------------- launch ----------------
extern "C" void kernel_launch(void* const* d_in, const int* in_sizes, int n_in,
                              void* d_out, int out_size) {
    const float* feat = (const float*)d_in[0];
    const int* src = (const int*)d_in[1];
    const int* dst = (const int*)d_in[2];
    const int* gid = (const int*)d_in[3];
    const float* Ws[6] = {(const float*)d_in[4], (const float*)d_in[6], (const float*)d_in[8],
                          (const float*)d_in[10], (const float*)d_in[12], (const float*)d_in[14]};
    const float* bs[6] = {(const float*)d_in[5], (const float*)d_in[7], (const float*)d_in[9],
                          (const float*)d_in[11], (const float*)d_in[13], (const float*)d_in[15]};
    const float* Wa = (const float*)d_in[16];
    const float* ba = (const float*)d_in[17];
    const float* Wb = (const float*)d_in[18];
    const float* bb = (const float*)d_in[19];
    float* out = (float*)d_out;

    const int SMEM_DYN = 4 * 128 * SA * 2;   // 139264 B
    cudaFuncSetAttribute(gemm_mma, cudaFuncAttributeMaxDynamicSharedMemorySize, SMEM_DYN);

    // graph structure + conversions: 4 launches
    setup_kernel<<<6250, 256>>>(feat, Ws[0], Ws[1], Ws[2], Ws[3], Ws[4], Ws[5]);
    degree_kernel<<<(N_EDGES + 255) / 256, 256>>>(src, dst);
    scanfull_kernel<<<SCAN_BLOCKS, 256>>>();
    fill_csr<<<(N_EDGES + 255) / 256, 256>>>(src, dst);

    const int AGG_GRID = (N_NODES * 32 + 255) / 256;

    // Layer 0: per-edge src norm on fp16 feat. GEMM epilogue pre-scales layers 0..4 by ns,
    // so layers 1..5 aggregate without per-edge norm loads. relu(x)*ns == relu(x*ns).
    aggregate_kernel<1, 1, 1><<<AGG_GRID, 256>>>(2, nullptr);
    gemm_mma<<<N_TILES, 512, SMEM_DYN>>>(bs[0], 0, 0, 1);

    for (int L = 1; L < 6; L++) {
        aggregate_kernel<0, 1, 1><<<AGG_GRID, 256>>>((L - 1) & 1, nullptr);
        gemm_mma<<<N_TILES, 512, SMEM_DYN>>>(bs[L], L, L & 1, (L < 5) ? 1 : 0);
    }
    // final features in g_h16[1]

    pool_kernel<<<SCAN_BLOCKS, 256>>>(1, gid);
    mlp_kernel<<<1, 256>>>(Wa, ba, Wb, bb, out);

    // unnormalized aggregation h_agg [50000,128] (fp32 accumulation from fp16 h6)
    aggregate_kernel<0, 0, 0><<<AGG_GRID, 256>>>(1, out + N_GRAPHS * N_CLASS);
}

// round 14
// speedup vs baseline: 1.2179x; 1.1055x over previous
#include <cuda_runtime.h>
#include <cuda_fp16.h>
#include <cstdint>

#define N_NODES 50000
#define N_EDGES 800000
#define DIM     128
#define N_GRAPHS 64
#define N_CLASS  10
#define HID      64
#define SCAN_BLOCKS 196   // ceil(50000/256)
#define N_TILES 391       // ceil(50000/128)
#define N_PAD   (N_TILES * 128)
#define SA      136       // padded K-stride in smem (bank-conflict-free fragments)

// ---------------- device scratch ----------------
__device__ __half g_h16[2][N_NODES * DIM];      // fp16 node features (ping-pong)
__device__ __half g_feat16[N_NODES * DIM];      // fp16 copy of input features
__device__ __half g_A16[N_PAD * DIM];           // fp16 aggregated feats (GEMM A), row-major
__device__ unsigned short g_Whi[6 * DIM * DIM]; // W^T [N][K] fp16 hi
__device__ unsigned short g_Wlo[6 * DIM * DIM]; // W^T [N][K] fp16 lo (residual)
__device__ float g_ns[N_NODES];
__device__ float g_nd[N_NODES];
__device__ int   g_indeg[N_NODES];
__device__ int   g_outdeg[N_NODES];
__device__ int   g_rowptr[N_NODES + 1];
__device__ int   g_cursor[N_NODES];   // initialized to rowptr by scanfull_kernel
__device__ int   g_csrsrc[N_EDGES];
__device__ float g_pooled[N_GRAPHS * DIM];
__device__ int   g_gcount[N_GRAPHS];

__device__ __forceinline__ void split_fp16(float x, unsigned short& hi, unsigned short& lo) {
    __half h = __float2half_rn(x);
    hi = __half_as_ushort(h);
    lo = __half_as_ushort(__float2half_rn(x - __half2float(h)));
}

// fp16 x fp16 -> fp32 accum MMA
__device__ __forceinline__ void mma16816_f16(float* c, const uint32_t* a, const uint32_t* b) {
    asm volatile(
        "mma.sync.aligned.m16n8k16.row.col.f32.f16.f16.f32 "
        "{%0,%1,%2,%3}, {%4,%5,%6,%7}, {%8,%9}, {%0,%1,%2,%3};"
        : "+f"(c[0]), "+f"(c[1]), "+f"(c[2]), "+f"(c[3])
        : "r"(a[0]), "r"(a[1]), "r"(a[2]), "r"(a[3]), "r"(b[0]), "r"(b[1]));
}

// ---------------- setup: feat->fp16, zero counters, tail tile, weight conversion ----------------
// grid = 6250 blocks x 256 = 1.6M threads (one float4 of feat each)
__global__ void setup_kernel(const float* __restrict__ feat,
                             const float* W0, const float* W1, const float* W2,
                             const float* W3, const float* W4, const float* W5) {
    int idx = blockIdx.x * 256 + threadIdx.x;

    // feat fp32 -> fp16 (float4 -> 2x half2)
    {
        float4 f = ((const float4*)feat)[idx];
        __half2 h01 = __floats2half2_rn(f.x, f.y);
        __half2 h23 = __floats2half2_rn(f.z, f.w);
        uint2 packed = make_uint2(*(uint32_t*)&h01, *(uint32_t*)&h23);
        ((uint2*)g_feat16)[idx] = packed;
    }

    if (idx < N_NODES) { g_indeg[idx] = 0; g_outdeg[idx] = 0; }
    if (idx < N_GRAPHS * DIM) g_pooled[idx] = 0.0f;
    if (idx < N_GRAPHS) g_gcount[idx] = 0;
    // zero padded tail rows (50000..50047) of A once
    if (idx < 768) ((uint4*)(g_A16 + N_NODES * DIM))[idx] = make_uint4(0, 0, 0, 0);

    if (idx < 6 * DIM * DIM) {
        int layer = idx >> 14;
        int r = idx & 16383;
        int n = r >> 7, k = r & 127;
        const float* Ws[6] = {W0, W1, W2, W3, W4, W5};
        float val = Ws[layer][k * DIM + n];
        unsigned short hi, lo;
        split_fp16(val, hi, lo);
        g_Whi[idx] = hi;
        g_Wlo[idx] = lo;
    }
}

__global__ void degree_kernel(const int* __restrict__ src, const int* __restrict__ dst) {
    int e = blockIdx.x * blockDim.x + threadIdx.x;
    if (e < N_EDGES) {
        atomicAdd(&g_outdeg[src[e]], 1);
        atomicAdd(&g_indeg[dst[e]], 1);
    }
}

// ---------------- norm + full exclusive scan of indeg -> rowptr (+cursor init), ONE launch ----------------
__global__ void scanfull_kernel() {
    __shared__ int ws[8];
    __shared__ int s[256];
    __shared__ int boff_sh;
    int t = threadIdx.x;
    int base = blockIdx.x * 256;
    int i = base + t;

    if (i < N_NODES) {
        g_ns[i] = rsqrtf((float)max(g_outdeg[i], 1));
        g_nd[i] = rsqrtf((float)max(g_indeg[i], 1));
    }

    int part = 0;
    for (int j = t; j < base; j += 256) part += g_indeg[j];
#pragma unroll
    for (int o = 16; o; o >>= 1) part += __shfl_down_sync(0xffffffffu, part, o);
    if ((t & 31) == 0) ws[t >> 5] = part;

    int v = (i < N_NODES) ? g_indeg[i] : 0;
    s[t] = v;
    __syncthreads();
    if (t == 0) {
        int b = 0;
#pragma unroll
        for (int w = 0; w < 8; w++) b += ws[w];
        boff_sh = b;
    }
    __syncthreads();
    int boff = boff_sh;

    for (int o = 1; o < 256; o <<= 1) {
        int x = (t >= o) ? s[t - o] : 0;
        __syncthreads();
        s[t] += x;
        __syncthreads();
    }
    if (i < N_NODES) {
        int r = boff + s[t] - v;
        g_rowptr[i] = r;
        g_cursor[i] = r;
        if (i == N_NODES - 1) g_rowptr[N_NODES] = r + v;
    }
}

// ---------------- CSR fill: cursor IS the slot ----------------
__global__ void fill_csr(const int* __restrict__ src, const int* __restrict__ dst) {
    int e = blockIdx.x * blockDim.x + threadIdx.x;
    if (e < N_EDGES) {
        int slot = atomicAdd(&g_cursor[dst[e]], 1);
        g_csrsrc[slot] = src[e];
    }
}

// ---------------- aggregation: fp16 input, one warp per dst node, 4x unrolled ----------------
// in_sel: 0/1 -> g_h16[sel], 2 -> g_feat16
// OUT_FP16=1: write fp16 A row-major (GEMM input). Else fp32 to ext_out.
template <int SRC_NORM, int DST_NORM, int OUT_FP16>
__global__ void aggregate_kernel(int in_sel, float* __restrict__ ext_out) {
    const __half* hin = (in_sel == 0) ? g_h16[0] : (in_sel == 1) ? g_h16[1] : g_feat16;

    int v = (blockIdx.x * blockDim.x + threadIdx.x) >> 5;
    if (v >= N_NODES) return;
    int lane = threadIdx.x & 31;

    int beg = g_rowptr[v];
    int end = g_rowptr[v + 1];

    const uint2* h2 = (const uint2*)hin;   // 4 halves per uint2; row = 32 uint2
    float4 acc = make_float4(0.f, 0.f, 0.f, 0.f);

    int i = beg;
    for (; i + 4 <= end; i += 4) {
        int s0 = g_csrsrc[i + 0];
        int s1 = g_csrsrc[i + 1];
        int s2 = g_csrsrc[i + 2];
        int s3 = g_csrsrc[i + 3];
        float w0 = SRC_NORM ? g_ns[s0] : 1.0f;
        float w1 = SRC_NORM ? g_ns[s1] : 1.0f;
        float w2 = SRC_NORM ? g_ns[s2] : 1.0f;
        float w3 = SRC_NORM ? g_ns[s3] : 1.0f;
        uint2 r0 = h2[s0 * 32 + lane];
        uint2 r1 = h2[s1 * 32 + lane];
        uint2 r2 = h2[s2 * 32 + lane];
        uint2 r3 = h2[s3 * 32 + lane];
        float2 a0 = __half22float2(*(__half2*)&r0.x), b0 = __half22float2(*(__half2*)&r0.y);
        float2 a1 = __half22float2(*(__half2*)&r1.x), b1 = __half22float2(*(__half2*)&r1.y);
        float2 a2 = __half22float2(*(__half2*)&r2.x), b2 = __half22float2(*(__half2*)&r2.y);
        float2 a3 = __half22float2(*(__half2*)&r3.x), b3 = __half22float2(*(__half2*)&r3.y);
        acc.x += w0 * a0.x; acc.y += w0 * a0.y; acc.z += w0 * b0.x; acc.w += w0 * b0.y;
        acc.x += w1 * a1.x; acc.y += w1 * a1.y; acc.z += w1 * b1.x; acc.w += w1 * b1.y;
        acc.x += w2 * a2.x; acc.y += w2 * a2.y; acc.z += w2 * b2.x; acc.w += w2 * b2.y;
        acc.x += w3 * a3.x; acc.y += w3 * a3.y; acc.z += w3 * b3.x; acc.w += w3 * b3.y;
    }
    for (; i < end; i++) {
        int s = g_csrsrc[i];
        float w = SRC_NORM ? g_ns[s] : 1.0f;
        uint2 rr = h2[s * 32 + lane];
        float2 aa = __half22float2(*(__half2*)&rr.x), bb = __half22float2(*(__half2*)&rr.y);
        acc.x += w * aa.x; acc.y += w * aa.y; acc.z += w * bb.x; acc.w += w * bb.y;
    }
    if (DST_NORM) {
        float sc = g_nd[v];
        acc.x *= sc; acc.y *= sc; acc.z *= sc; acc.w *= sc;
    }

    if (OUT_FP16) {
        __half2 h01 = __floats2half2_rn(acc.x, acc.y);
        __half2 h23 = __floats2half2_rn(acc.z, acc.w);
        uint2 packed = make_uint2(*(uint32_t*)&h01, *(uint32_t*)&h23);
        *(uint2*)&g_A16[(size_t)v * DIM + lane * 4] = packed;
    } else {
        ((float4*)ext_out)[v * 32 + lane] = acc;
    }
}

// ---------------- tensor-core GEMM: fp16 A (exact) x fp16-split W, 2 MMA passes ----------------
// 512 threads = 16 warps (4M x 4N), warp tile 32x32.
// g_h16[out_buf][row] = fp16( relu(A[row] @ W + b) * (do_ps ? g_ns[row] : 1) )
__global__ void __launch_bounds__(512) gemm_mma(
    const float* __restrict__ b, int layer, int out_buf, int do_ps) {
    extern __shared__ __align__(16) unsigned short sm[];
    unsigned short* sA  = sm;                    // 128 x SA fp16
    unsigned short* sWh = sm + 128 * SA;         // 128 x SA fp16
    unsigned short* sWl = sm + 2 * 128 * SA;     // 128 x SA fp16

    int tid = threadIdx.x;
    const uint4* gA  = (const uint4*)(g_A16 + (size_t)blockIdx.x * (128 * DIM));
    const uint4* gWh = (const uint4*)(g_Whi + (size_t)layer * (DIM * DIM));
    const uint4* gWl = (const uint4*)(g_Wlo + (size_t)layer * (DIM * DIM));

    // stage tiles: 2048 uint4 each, 512 threads -> 4 per thread per buffer
#pragma unroll
    for (int it = 0; it < 4; it++) {
        int i = tid + it * 512;
        int r = i >> 4, c = (i & 15) << 3;
        *(uint4*)&sA[r * SA + c]  = gA[i];
        *(uint4*)&sWh[r * SA + c] = gWh[i];
        *(uint4*)&sWl[r * SA + c] = gWl[i];
    }
    __syncthreads();

    int warp = tid >> 5, lane = tid & 31;
    int wm = warp & 3, wn = warp >> 2;           // 4 M-warps x 4 N-warps
    int bm = wm * 32, bn = wn * 32;
    int lr = lane >> 2, lc = (lane & 3) * 2;

    float acc[2][4][4];
#pragma unroll
    for (int mi = 0; mi < 2; mi++)
#pragma unroll
        for (int ni = 0; ni < 4; ni++)
#pragma unroll
            for (int q = 0; q < 4; q++) acc[mi][ni][q] = 0.f;

#pragma unroll
    for (int k = 0; k < 8; k++) {
        int k0 = k * 16;
        uint32_t af[2][4], bfh[4][2], bfl[4][2];
#pragma unroll
        for (int mi = 0; mi < 2; mi++) {
            int r = bm + mi * 16 + lr;
            af[mi][0] = *(const uint32_t*)&sA[r * SA + k0 + lc];
            af[mi][1] = *(const uint32_t*)&sA[(r + 8) * SA + k0 + lc];
            af[mi][2] = *(const uint32_t*)&sA[r * SA + k0 + 8 + lc];
            af[mi][3] = *(const uint32_t*)&sA[(r + 8) * SA + k0 + 8 + lc];
        }
#pragma unroll
        for (int ni = 0; ni < 4; ni++) {
            int cc = bn + ni * 8 + lr;
            bfh[ni][0] = *(const uint32_t*)&sWh[cc * SA + k0 + lc];
            bfh[ni][1] = *(const uint32_t*)&sWh[cc * SA + k0 + 8 + lc];
            bfl[ni][0] = *(const uint32_t*)&sWl[cc * SA + k0 + lc];
            bfl[ni][1] = *(const uint32_t*)&sWl[cc * SA + k0 + 8 + lc];
        }
#pragma unroll
        for (int mi = 0; mi < 2; mi++)
#pragma unroll
            for (int ni = 0; ni < 4; ni++) {
                mma16816_f16(acc[mi][ni], af[mi], bfh[ni]);   // A * Whi
                mma16816_f16(acc[mi][ni], af[mi], bfl[ni]);   // A * Wlo
            }
    }

    __half* C = g_h16[out_buf];
#pragma unroll
    for (int mi = 0; mi < 2; mi++) {
        int r0 = blockIdx.x * 128 + bm + mi * 16 + lr;
        int r1 = r0 + 8;
        float ps0 = 1.f, ps1 = 1.f;
        if (do_ps) {
            if (r0 < N_NODES) ps0 = g_ns[r0];
            if (r1 < N_NODES) ps1 = g_ns[r1];
        }
#pragma unroll
        for (int ni = 0; ni < 4; ni++) {
            int col = bn + ni * 8 + lc;
            float2 bv = *(const float2*)&b[col];
            if (r0 < N_NODES) {
                float ox = fmaxf(acc[mi][ni][0] + bv.x, 0.f) * ps0;
                float oy = fmaxf(acc[mi][ni][1] + bv.y, 0.f) * ps0;
                *(__half2*)&C[(size_t)r0 * DIM + col] = __floats2half2_rn(ox, oy);
            }
            if (r1 < N_NODES) {
                float ox = fmaxf(acc[mi][ni][2] + bv.x, 0.f) * ps1;
                float oy = fmaxf(acc[mi][ni][3] + bv.y, 0.f) * ps1;
                *(__half2*)&C[(size_t)r1 * DIM + col] = __floats2half2_rn(ox, oy);
            }
        }
    }
}

// ---------------- pooling: sorted graph_id -> register accumulation ----------------
__global__ void pool_kernel(int buf, const int* __restrict__ gid) {
    const __half* h = g_h16[buf];
    int group = blockIdx.x * 2 + (threadIdx.x >> 7);
    int d = threadIdx.x & 127;
    int start = group * 128;
    if (start >= N_NODES) return;
    int end = min(start + 128, N_NODES);

    int cur = gid[start];
    float acc = 0.f;
    int cnt = 0;
    for (int n = start; n < end; n++) {
        int g = gid[n];
        if (g != cur) {
            atomicAdd(&g_pooled[cur * DIM + d], acc);
            if (d == 0) atomicAdd(&g_gcount[cur], cnt);
            acc = 0.f; cnt = 0; cur = g;
        }
        acc += __half2float(h[n * DIM + d]);
        cnt++;
    }
    atomicAdd(&g_pooled[cur * DIM + d], acc);
    if (d == 0) atomicAdd(&g_gcount[cur], cnt);
}

// ---------------- head MLP ----------------
__global__ void mlp_kernel(const float* __restrict__ Wa, const float* __restrict__ ba,
                           const float* __restrict__ Wb, const float* __restrict__ bb,
                           float* __restrict__ out) {
    __shared__ float pm[N_GRAPHS * DIM];
    __shared__ float z[N_GRAPHS * HID];
    int t = threadIdx.x;

    for (int i = t; i < N_GRAPHS * DIM; i += 256) {
        int g = i / DIM;
        float cnt = fmaxf((float)g_gcount[g], 1.0f);
        pm[i] = g_pooled[i] / cnt;
    }
    __syncthreads();

    for (int i = t; i < N_GRAPHS * HID; i += 256) {
        int g = i / HID, j = i % HID;
        float s = ba[j];
        for (int d = 0; d < DIM; d++) s += pm[g * DIM + d] * Wa[d * HID + j];
        z[i] = fmaxf(s, 0.0f);
    }
    __syncthreads();

    for (int i = t; i < N_GRAPHS * N_CLASS; i += 256) {
        int g = i / N_CLASS, c = i % N_CLASS;
        float s = bb[c];
        for (int j = 0; j < HID; j++) s += z[g * HID + j] * Wb[j * N_CLASS + c];
        out[i] = s;
    }
}

// ---------------- launch ----------------
extern "C" void kernel_launch(void* const* d_in, const int* in_sizes, int n_in,
                              void* d_out, int out_size) {
    const float* feat = (const float*)d_in[0];
    const int* src = (const int*)d_in[1];
    const int* dst = (const int*)d_in[2];
    const int* gid = (const int*)d_in[3];
    const float* Ws[6] = {(const float*)d_in[4], (const float*)d_in[6], (const float*)d_in[8],
                          (const float*)d_in[10], (const float*)d_in[12], (const float*)d_in[14]};
    const float* bs[6] = {(const float*)d_in[5], (const float*)d_in[7], (const float*)d_in[9],
                          (const float*)d_in[11], (const float*)d_in[13], (const float*)d_in[15]};
    const float* Wa = (const float*)d_in[16];
    const float* ba = (const float*)d_in[17];
    const float* Wb = (const float*)d_in[18];
    const float* bb = (const float*)d_in[19];
    float* out = (float*)d_out;

    const int SMEM_DYN = 3 * 128 * SA * 2;   // 104448 B -> 2 CTAs/SM possible
    cudaFuncSetAttribute(gemm_mma, cudaFuncAttributeMaxDynamicSharedMemorySize, SMEM_DYN);

    // graph structure + conversions: 4 launches
    setup_kernel<<<6250, 256>>>(feat, Ws[0], Ws[1], Ws[2], Ws[3], Ws[4], Ws[5]);
    degree_kernel<<<(N_EDGES + 255) / 256, 256>>>(src, dst);
    scanfull_kernel<<<SCAN_BLOCKS, 256>>>();
    fill_csr<<<(N_EDGES + 255) / 256, 256>>>(src, dst);

    const int AGG_GRID = (N_NODES * 32 + 255) / 256;

    // Layer 0: per-edge src norm on fp16 feat. GEMM epilogue pre-scales layers 0..4 by ns,
    // so layers 1..5 aggregate without per-edge norm loads. relu(x)*ns == relu(x*ns).
    aggregate_kernel<1, 1, 1><<<AGG_GRID, 256>>>(2, nullptr);
    gemm_mma<<<N_TILES, 512, SMEM_DYN>>>(bs[0], 0, 0, 1);

    for (int L = 1; L < 6; L++) {
        aggregate_kernel<0, 1, 1><<<AGG_GRID, 256>>>((L - 1) & 1, nullptr);
        gemm_mma<<<N_TILES, 512, SMEM_DYN>>>(bs[L], L, L & 1, (L < 5) ? 1 : 0);
    }
    // final features in g_h16[1]

    pool_kernel<<<SCAN_BLOCKS, 256>>>(1, gid);
    mlp_kernel<<<1, 256>>>(Wa, ba, Wb, bb, out);

    // unnormalized aggregation h_agg [50000,128] (fp32 accumulation from fp16 h6)
    aggregate_kernel<0, 0, 0><<<AGG_GRID, 256>>>(1, out + N_GRAPHS * N_CLASS);
}

// round 15
// speedup vs baseline: 1.2419x; 1.0198x over previous
#include <cuda_runtime.h>
#include <cuda_fp16.h>
#include <cstdint>

#define N_NODES 50000
#define N_EDGES 800000
#define DIM     128
#define N_GRAPHS 64
#define N_CLASS  10
#define HID      64
#define SCAN_BLOCKS 196   // ceil(50000/256)
#define N_TILES 391       // ceil(50000/128)
#define N_PAD   (N_TILES * 128)
#define SA      136       // padded K-stride in smem (bank-conflict-free fragments)

// ---------------- device scratch ----------------
__device__ __half g_h16[2][N_NODES * DIM];      // fp16 node features (ping-pong)
__device__ __half g_feat16[N_NODES * DIM];      // fp16 copy of input features
__device__ __half g_A16[N_PAD * DIM];           // fp16 aggregated feats (GEMM A), row-major
__device__ unsigned short g_Whi[6 * DIM * DIM]; // W^T [N][K] fp16 hi
__device__ unsigned short g_Wlo[6 * DIM * DIM]; // W^T [N][K] fp16 lo (residual)
__device__ float g_ns[N_NODES];
__device__ float g_nd[N_NODES];
__device__ int   g_indeg[N_NODES];
__device__ int   g_outdeg[N_NODES];
__device__ int   g_rowptr[N_NODES + 1];
__device__ int   g_cursor[N_NODES];   // initialized to rowptr by scanfull_kernel
__device__ int   g_csrsrc[N_EDGES];
__device__ float g_pooled[N_GRAPHS * DIM];
__device__ int   g_gcount[N_GRAPHS];

__device__ __forceinline__ void split_fp16(float x, unsigned short& hi, unsigned short& lo) {
    __half h = __float2half_rn(x);
    hi = __half_as_ushort(h);
    lo = __half_as_ushort(__float2half_rn(x - __half2float(h)));
}

// fp16 x fp16 -> fp32 accum MMA
__device__ __forceinline__ void mma16816_f16(float* c, const uint32_t* a, const uint32_t* b) {
    asm volatile(
        "mma.sync.aligned.m16n8k16.row.col.f32.f16.f16.f32 "
        "{%0,%1,%2,%3}, {%4,%5,%6,%7}, {%8,%9}, {%0,%1,%2,%3};"
        : "+f"(c[0]), "+f"(c[1]), "+f"(c[2]), "+f"(c[3])
        : "r"(a[0]), "r"(a[1]), "r"(a[2]), "r"(a[3]), "r"(b[0]), "r"(b[1]));
}

// ---------------- setup: feat->fp16, zero counters, tail tile, weight conversion ----------------
__global__ void setup_kernel(const float* __restrict__ feat,
                             const float* W0, const float* W1, const float* W2,
                             const float* W3, const float* W4, const float* W5) {
    int idx = blockIdx.x * 256 + threadIdx.x;

    // feat fp32 -> fp16 (float4 -> 2x half2)
    {
        float4 f = ((const float4*)feat)[idx];
        __half2 h01 = __floats2half2_rn(f.x, f.y);
        __half2 h23 = __floats2half2_rn(f.z, f.w);
        uint2 packed = make_uint2(*(uint32_t*)&h01, *(uint32_t*)&h23);
        ((uint2*)g_feat16)[idx] = packed;
    }

    if (idx < N_NODES) { g_indeg[idx] = 0; g_outdeg[idx] = 0; }
    if (idx < N_GRAPHS * DIM) g_pooled[idx] = 0.0f;
    if (idx < N_GRAPHS) g_gcount[idx] = 0;
    if (idx < 768) ((uint4*)(g_A16 + N_NODES * DIM))[idx] = make_uint4(0, 0, 0, 0);

    if (idx < 6 * DIM * DIM) {
        int layer = idx >> 14;
        int r = idx & 16383;
        int n = r >> 7, k = r & 127;
        const float* Ws[6] = {W0, W1, W2, W3, W4, W5};
        float val = Ws[layer][k * DIM + n];
        unsigned short hi, lo;
        split_fp16(val, hi, lo);
        g_Whi[idx] = hi;
        g_Wlo[idx] = lo;
    }
}

__global__ void degree_kernel(const int* __restrict__ src, const int* __restrict__ dst) {
    int e = blockIdx.x * blockDim.x + threadIdx.x;
    if (e < N_EDGES) {
        atomicAdd(&g_outdeg[src[e]], 1);
        atomicAdd(&g_indeg[dst[e]], 1);
    }
}

// ---------------- norm + full exclusive scan of indeg -> rowptr (+cursor init), ONE launch ----------------
__global__ void scanfull_kernel() {
    __shared__ int ws[8];
    __shared__ int s[256];
    __shared__ int boff_sh;
    int t = threadIdx.x;
    int base = blockIdx.x * 256;
    int i = base + t;

    if (i < N_NODES) {
        g_ns[i] = rsqrtf((float)max(g_outdeg[i], 1));
        g_nd[i] = rsqrtf((float)max(g_indeg[i], 1));
    }

    int part = 0;
    for (int j = t; j < base; j += 256) part += g_indeg[j];
#pragma unroll
    for (int o = 16; o; o >>= 1) part += __shfl_down_sync(0xffffffffu, part, o);
    if ((t & 31) == 0) ws[t >> 5] = part;

    int v = (i < N_NODES) ? g_indeg[i] : 0;
    s[t] = v;
    __syncthreads();
    if (t == 0) {
        int b = 0;
#pragma unroll
        for (int w = 0; w < 8; w++) b += ws[w];
        boff_sh = b;
    }
    __syncthreads();
    int boff = boff_sh;

    for (int o = 1; o < 256; o <<= 1) {
        int x = (t >= o) ? s[t - o] : 0;
        __syncthreads();
        s[t] += x;
        __syncthreads();
    }
    if (i < N_NODES) {
        int r = boff + s[t] - v;
        g_rowptr[i] = r;
        g_cursor[i] = r;
        if (i == N_NODES - 1) g_rowptr[N_NODES] = r + v;
    }
}

// ---------------- CSR fill: cursor IS the slot ----------------
__global__ void fill_csr(const int* __restrict__ src, const int* __restrict__ dst) {
    int e = blockIdx.x * blockDim.x + threadIdx.x;
    if (e < N_EDGES) {
        int slot = atomicAdd(&g_cursor[dst[e]], 1);
        g_csrsrc[slot] = src[e];
    }
}

// ---------------- aggregation: fp16 input, one warp per dst node, 8x unrolled ----------------
// in_sel: 0/1 -> g_h16[sel], 2 -> g_feat16
// OUT_FP16=1: write fp16 A row-major (GEMM input). Else fp32 to ext_out.
template <int SRC_NORM, int DST_NORM, int OUT_FP16>
__global__ void aggregate_kernel(int in_sel, float* __restrict__ ext_out) {
    const __half* hin = (in_sel == 0) ? g_h16[0] : (in_sel == 1) ? g_h16[1] : g_feat16;

    int v = (blockIdx.x * blockDim.x + threadIdx.x) >> 5;
    if (v >= N_NODES) return;
    int lane = threadIdx.x & 31;

    int beg = g_rowptr[v];
    int end = g_rowptr[v + 1];

    const uint2* h2 = (const uint2*)hin;   // 4 halves per uint2; row = 32 uint2
    float4 acc = make_float4(0.f, 0.f, 0.f, 0.f);

    int i = beg;
    // 8x unroll: 8 independent index loads -> 8 independent row loads in flight
    for (; i + 8 <= end; i += 8) {
        int s[8];
#pragma unroll
        for (int u = 0; u < 8; u++) s[u] = g_csrsrc[i + u];
        float w[8];
#pragma unroll
        for (int u = 0; u < 8; u++) w[u] = SRC_NORM ? g_ns[s[u]] : 1.0f;
        uint2 r[8];
#pragma unroll
        for (int u = 0; u < 8; u++) r[u] = h2[s[u] * 32 + lane];
#pragma unroll
        for (int u = 0; u < 8; u++) {
            float2 aa = __half22float2(*(__half2*)&r[u].x);
            float2 bb = __half22float2(*(__half2*)&r[u].y);
            acc.x += w[u] * aa.x; acc.y += w[u] * aa.y;
            acc.z += w[u] * bb.x; acc.w += w[u] * bb.y;
        }
    }
    for (; i < end; i++) {
        int s = g_csrsrc[i];
        float w = SRC_NORM ? g_ns[s] : 1.0f;
        uint2 rr = h2[s * 32 + lane];
        float2 aa = __half22float2(*(__half2*)&rr.x), bb = __half22float2(*(__half2*)&rr.y);
        acc.x += w * aa.x; acc.y += w * aa.y; acc.z += w * bb.x; acc.w += w * bb.y;
    }
    if (DST_NORM) {
        float sc = g_nd[v];
        acc.x *= sc; acc.y *= sc; acc.z *= sc; acc.w *= sc;
    }

    if (OUT_FP16) {
        __half2 h01 = __floats2half2_rn(acc.x, acc.y);
        __half2 h23 = __floats2half2_rn(acc.z, acc.w);
        uint2 packed = make_uint2(*(uint32_t*)&h01, *(uint32_t*)&h23);
        *(uint2*)&g_A16[(size_t)v * DIM + lane * 4] = packed;
    } else {
        ((float4*)ext_out)[v * 32 + lane] = acc;
    }
}

// ---------------- tensor-core GEMM: fp16 A (exact) x fp16-split W, 2 MMA passes ----------------
// 512 threads = 16 warps (4M x 4N), warp tile 32x32.
__global__ void __launch_bounds__(512) gemm_mma(
    const float* __restrict__ b, int layer, int out_buf, int do_ps) {
    extern __shared__ __align__(16) unsigned short sm[];
    unsigned short* sA  = sm;                    // 128 x SA fp16
    unsigned short* sWh = sm + 128 * SA;
    unsigned short* sWl = sm + 2 * 128 * SA;

    int tid = threadIdx.x;
    const uint4* gA  = (const uint4*)(g_A16 + (size_t)blockIdx.x * (128 * DIM));
    const uint4* gWh = (const uint4*)(g_Whi + (size_t)layer * (DIM * DIM));
    const uint4* gWl = (const uint4*)(g_Wlo + (size_t)layer * (DIM * DIM));

#pragma unroll
    for (int it = 0; it < 4; it++) {
        int i = tid + it * 512;
        int r = i >> 4, c = (i & 15) << 3;
        *(uint4*)&sA[r * SA + c]  = gA[i];
        *(uint4*)&sWh[r * SA + c] = gWh[i];
        *(uint4*)&sWl[r * SA + c] = gWl[i];
    }
    __syncthreads();

    int warp = tid >> 5, lane = tid & 31;
    int wm = warp & 3, wn = warp >> 2;           // 4 M-warps x 4 N-warps
    int bm = wm * 32, bn = wn * 32;
    int lr = lane >> 2, lc = (lane & 3) * 2;

    float acc[2][4][4];
#pragma unroll
    for (int mi = 0; mi < 2; mi++)
#pragma unroll
        for (int ni = 0; ni < 4; ni++)
#pragma unroll
            for (int q = 0; q < 4; q++) acc[mi][ni][q] = 0.f;

#pragma unroll
    for (int k = 0; k < 8; k++) {
        int k0 = k * 16;
        uint32_t af[2][4], bfh[4][2], bfl[4][2];
#pragma unroll
        for (int mi = 0; mi < 2; mi++) {
            int r = bm + mi * 16 + lr;
            af[mi][0] = *(const uint32_t*)&sA[r * SA + k0 + lc];
            af[mi][1] = *(const uint32_t*)&sA[(r + 8) * SA + k0 + lc];
            af[mi][2] = *(const uint32_t*)&sA[r * SA + k0 + 8 + lc];
            af[mi][3] = *(const uint32_t*)&sA[(r + 8) * SA + k0 + 8 + lc];
        }
#pragma unroll
        for (int ni = 0; ni < 4; ni++) {
            int cc = bn + ni * 8 + lr;
            bfh[ni][0] = *(const uint32_t*)&sWh[cc * SA + k0 + lc];
            bfh[ni][1] = *(const uint32_t*)&sWh[cc * SA + k0 + 8 + lc];
            bfl[ni][0] = *(const uint32_t*)&sWl[cc * SA + k0 + lc];
            bfl[ni][1] = *(const uint32_t*)&sWl[cc * SA + k0 + 8 + lc];
        }
#pragma unroll
        for (int mi = 0; mi < 2; mi++)
#pragma unroll
            for (int ni = 0; ni < 4; ni++) {
                mma16816_f16(acc[mi][ni], af[mi], bfh[ni]);   // A * Whi
                mma16816_f16(acc[mi][ni], af[mi], bfl[ni]);   // A * Wlo
            }
    }

    __half* C = g_h16[out_buf];
#pragma unroll
    for (int mi = 0; mi < 2; mi++) {
        int r0 = blockIdx.x * 128 + bm + mi * 16 + lr;
        int r1 = r0 + 8;
        float ps0 = 1.f, ps1 = 1.f;
        if (do_ps) {
            if (r0 < N_NODES) ps0 = g_ns[r0];
            if (r1 < N_NODES) ps1 = g_ns[r1];
        }
#pragma unroll
        for (int ni = 0; ni < 4; ni++) {
            int col = bn + ni * 8 + lc;
            float2 bv = *(const float2*)&b[col];
            if (r0 < N_NODES) {
                float ox = fmaxf(acc[mi][ni][0] + bv.x, 0.f) * ps0;
                float oy = fmaxf(acc[mi][ni][1] + bv.y, 0.f) * ps0;
                *(__half2*)&C[(size_t)r0 * DIM + col] = __floats2half2_rn(ox, oy);
            }
            if (r1 < N_NODES) {
                float ox = fmaxf(acc[mi][ni][2] + bv.x, 0.f) * ps1;
                float oy = fmaxf(acc[mi][ni][3] + bv.y, 0.f) * ps1;
                *(__half2*)&C[(size_t)r1 * DIM + col] = __floats2half2_rn(ox, oy);
            }
        }
    }
}

// ---------------- pooling: sorted graph_id -> register accumulation ----------------
__global__ void pool_kernel(int buf, const int* __restrict__ gid) {
    const __half* h = g_h16[buf];
    int group = blockIdx.x * 2 + (threadIdx.x >> 7);
    int d = threadIdx.x & 127;
    int start = group * 128;
    if (start >= N_NODES) return;
    int end = min(start + 128, N_NODES);

    int cur = gid[start];
    float acc = 0.f;
    int cnt = 0;
    for (int n = start; n < end; n++) {
        int g = gid[n];
        if (g != cur) {
            atomicAdd(&g_pooled[cur * DIM + d], acc);
            if (d == 0) atomicAdd(&g_gcount[cur], cnt);
            acc = 0.f; cnt = 0; cur = g;
        }
        acc += __half2float(h[n * DIM + d]);
        cnt++;
    }
    atomicAdd(&g_pooled[cur * DIM + d], acc);
    if (d == 0) atomicAdd(&g_gcount[cur], cnt);
}

// ---------------- head MLP ----------------
__global__ void mlp_kernel(const float* __restrict__ Wa, const float* __restrict__ ba,
                           const float* __restrict__ Wb, const float* __restrict__ bb,
                           float* __restrict__ out) {
    __shared__ float pm[N_GRAPHS * DIM];
    __shared__ float z[N_GRAPHS * HID];
    int t = threadIdx.x;

    for (int i = t; i < N_GRAPHS * DIM; i += 256) {
        int g = i / DIM;
        float cnt = fmaxf((float)g_gcount[g], 1.0f);
        pm[i] = g_pooled[i] / cnt;
    }
    __syncthreads();

    for (int i = t; i < N_GRAPHS * HID; i += 256) {
        int g = i / HID, j = i % HID;
        float s = ba[j];
        for (int d = 0; d < DIM; d++) s += pm[g * DIM + d] * Wa[d * HID + j];
        z[i] = fmaxf(s, 0.0f);
    }
    __syncthreads();

    for (int i = t; i < N_GRAPHS * N_CLASS; i += 256) {
        int g = i / N_CLASS, c = i % N_CLASS;
        float s = bb[c];
        for (int j = 0; j < HID; j++) s += z[g * HID + j] * Wb[j * N_CLASS + c];
        out[i] = s;
    }
}

// ---------------- launch ----------------
extern "C" void kernel_launch(void* const* d_in, const int* in_sizes, int n_in,
                              void* d_out, int out_size) {
    const float* feat = (const float*)d_in[0];
    const int* src = (const int*)d_in[1];
    const int* dst = (const int*)d_in[2];
    const int* gid = (const int*)d_in[3];
    const float* Ws[6] = {(const float*)d_in[4], (const float*)d_in[6], (const float*)d_in[8],
                          (const float*)d_in[10], (const float*)d_in[12], (const float*)d_in[14]};
    const float* bs[6] = {(const float*)d_in[5], (const float*)d_in[7], (const float*)d_in[9],
                          (const float*)d_in[11], (const float*)d_in[13], (const float*)d_in[15]};
    const float* Wa = (const float*)d_in[16];
    const float* ba = (const float*)d_in[17];
    const float* Wb = (const float*)d_in[18];
    const float* bb = (const float*)d_in[19];
    float* out = (float*)d_out;

    const int SMEM_DYN = 3 * 128 * SA * 2;   // 104448 B
    cudaFuncSetAttribute(gemm_mma, cudaFuncAttributeMaxDynamicSharedMemorySize, SMEM_DYN);

    // graph structure + conversions: 4 launches
    setup_kernel<<<6250, 256>>>(feat, Ws[0], Ws[1], Ws[2], Ws[3], Ws[4], Ws[5]);
    degree_kernel<<<(N_EDGES + 255) / 256, 256>>>(src, dst);
    scanfull_kernel<<<SCAN_BLOCKS, 256>>>();
    fill_csr<<<(N_EDGES + 255) / 256, 256>>>(src, dst);

    const int AGG_GRID = (N_NODES * 32 + 255) / 256;

    // Layer 0: per-edge src norm on fp16 feat. GEMM epilogue pre-scales layers 0..4 by ns,
    // so layers 1..5 aggregate without per-edge norm loads. relu(x)*ns == relu(x*ns).
    aggregate_kernel<1, 1, 1><<<AGG_GRID, 256>>>(2, nullptr);
    gemm_mma<<<N_TILES, 512, SMEM_DYN>>>(bs[0], 0, 0, 1);

    for (int L = 1; L < 6; L++) {
        aggregate_kernel<0, 1, 1><<<AGG_GRID, 256>>>((L - 1) & 1, nullptr);
        gemm_mma<<<N_TILES, 512, SMEM_DYN>>>(bs[L], L, L & 1, (L < 5) ? 1 : 0);
    }
    // final features in g_h16[1]

    pool_kernel<<<SCAN_BLOCKS, 256>>>(1, gid);
    mlp_kernel<<<1, 256>>>(Wa, ba, Wb, bb, out);

    // unnormalized aggregation h_agg [50000,128] (fp32 accumulation from fp16 h6)
    aggregate_kernel<0, 0, 0><<<AGG_GRID, 256>>>(1, out + N_GRAPHS * N_CLASS);
}